// round 1
// baseline (speedup 1.0000x reference)
#include <cuda_runtime.h>
#include <math.h>

// Problem constants
constexpr int L    = 3072;
constexpr int D    = 1024;
constexpr int H    = 16;
constexpr int HD   = 64;
constexpr int SCTX = 512;
constexpr int DFF  = 4096;
constexpr int NB   = 2;

// ---------------- scratch (static device arrays; no cudaMalloc allowed) ----
__device__ float g_hx[(size_t)L * D];
__device__ float g_q [(size_t)L * D];
__device__ float g_k [(size_t)L * D];
__device__ float g_v [(size_t)L * D];
__device__ float g_o [(size_t)L * D];
__device__ float g_ck[(size_t)SCTX * D];
__device__ float g_cv[(size_t)SCTX * D];
__device__ float g_h [(size_t)L * DFF];
__device__ float g_mods[6 * D];

enum { EP_STORE = 0, EP_GELU = 1, EP_RESID = 2, EP_RESID_GATE = 3 };

// ---------------------------------------------------------------------------
// GEMM: C[M,N] (+epilogue) from A[M,K] (row-major) x W[N,K] (row-major, NT)
// BM=BN=128, BK=8, 256 threads, 8x8 microtile per thread.
// ---------------------------------------------------------------------------
__global__ void __launch_bounds__(256, 2) gemm_nt(
    const float* __restrict__ A, const float* __restrict__ W,
    const float* __restrict__ bias, const float* __restrict__ gate,
    float* __restrict__ C, int M, int N, int K, int mode)
{
    __shared__ float As[8][132];
    __shared__ float Bs[8][132];

    const int tid = threadIdx.x;
    const int m0 = blockIdx.y * 128;
    const int n0 = blockIdx.x * 128;
    const int tx = tid & 15, ty = tid >> 4;
    const int lrow = tid >> 1;          // 0..127
    const int lcol = (tid & 1) * 4;     // 0 or 4

    const float* Ap = A + (size_t)(m0 + lrow) * K + lcol;
    const float* Wp = W + (size_t)(n0 + lrow) * K + lcol;

    float acc[8][8];
#pragma unroll
    for (int i = 0; i < 8; i++)
#pragma unroll
        for (int j = 0; j < 8; j++) acc[i][j] = 0.f;

    for (int k0 = 0; k0 < K; k0 += 8) {
        float4 av = *reinterpret_cast<const float4*>(Ap + k0);
        float4 wv = *reinterpret_cast<const float4*>(Wp + k0);
        As[lcol + 0][lrow] = av.x; As[lcol + 1][lrow] = av.y;
        As[lcol + 2][lrow] = av.z; As[lcol + 3][lrow] = av.w;
        Bs[lcol + 0][lrow] = wv.x; Bs[lcol + 1][lrow] = wv.y;
        Bs[lcol + 2][lrow] = wv.z; Bs[lcol + 3][lrow] = wv.w;
        __syncthreads();
#pragma unroll
        for (int k = 0; k < 8; k++) {
            float a[8], b[8];
            *reinterpret_cast<float4*>(a)     = *reinterpret_cast<const float4*>(&As[k][ty * 8]);
            *reinterpret_cast<float4*>(a + 4) = *reinterpret_cast<const float4*>(&As[k][ty * 8 + 4]);
            *reinterpret_cast<float4*>(b)     = *reinterpret_cast<const float4*>(&Bs[k][tx * 8]);
            *reinterpret_cast<float4*>(b + 4) = *reinterpret_cast<const float4*>(&Bs[k][tx * 8 + 4]);
#pragma unroll
            for (int i = 0; i < 8; i++)
#pragma unroll
                for (int j = 0; j < 8; j++)
                    acc[i][j] = fmaf(a[i], b[j], acc[i][j]);
        }
        __syncthreads();
    }

    const int r = m0 + ty * 8;
    const int c = n0 + tx * 8;
    float bv[8], gv[8];
#pragma unroll
    for (int j = 0; j < 8; j++) {
        bv[j] = bias ? bias[c + j] : 0.f;
        gv[j] = gate ? gate[c + j] : 1.f;
    }
#pragma unroll
    for (int i = 0; i < 8; i++) {
        float* Cp = C + (size_t)(r + i) * N + c;
#pragma unroll
        for (int j = 0; j < 8; j++) {
            float val = acc[i][j] + bv[j];
            if (mode == EP_STORE) {
                Cp[j] = val;
            } else if (mode == EP_GELU) {
                Cp[j] = 0.5f * val * (1.f + erff(val * 0.70710678118654752f));
            } else if (mode == EP_RESID) {
                Cp[j] += val;
            } else { // EP_RESID_GATE
                Cp[j] += gv[j] * val;
            }
        }
    }
}

// ---------------------------------------------------------------------------
// adaLN modulation GEMV: out[6D] = t[D] @ W[6D,D]^T + b  (warp per output)
// ---------------------------------------------------------------------------
__global__ void __launch_bounds__(256) gemv_ada(
    const float* __restrict__ t, const float* __restrict__ Wt,
    const float* __restrict__ b, float* __restrict__ out)
{
    const int o    = blockIdx.x * 8 + (threadIdx.x >> 5);
    const int lane = threadIdx.x & 31;
    const float* wr = Wt + (size_t)o * D;
    float s = 0.f;
    for (int d = lane; d < D; d += 32) s = fmaf(t[d], wr[d], s);
#pragma unroll
    for (int off = 16; off; off >>= 1) s += __shfl_xor_sync(0xffffffffu, s, off);
    if (lane == 0) out[o] = s + b[o];
}

// ---------------------------------------------------------------------------
// LayerNorm (+ optional adaLN shift/scale): y = LN(x)*(1+sc)+sh
// One block per row, 256 threads, 4 elems/thread.
// ---------------------------------------------------------------------------
__global__ void __launch_bounds__(256) ln_mod_kernel(
    const float* __restrict__ x, const float* __restrict__ mods,
    int sh_off, int sc_off, float* __restrict__ y)
{
    __shared__ float red[8];
    __shared__ float bval;
    const int row = blockIdx.x;
    const int t = threadIdx.x;
    const float* xr = x + (size_t)row * D;

    float v[4];
    float s = 0.f;
#pragma unroll
    for (int j = 0; j < 4; j++) { v[j] = xr[t + j * 256]; s += v[j]; }
#pragma unroll
    for (int off = 16; off; off >>= 1) s += __shfl_xor_sync(0xffffffffu, s, off);
    if ((t & 31) == 0) red[t >> 5] = s;
    __syncthreads();
    if (t == 0) {
        float tot = 0.f;
        for (int j = 0; j < 8; j++) tot += red[j];
        bval = tot * (1.f / D);
    }
    __syncthreads();
    const float mean = bval;

    float vs = 0.f;
#pragma unroll
    for (int j = 0; j < 4; j++) { float d = v[j] - mean; vs = fmaf(d, d, vs); }
#pragma unroll
    for (int off = 16; off; off >>= 1) vs += __shfl_xor_sync(0xffffffffu, vs, off);
    if ((t & 31) == 0) red[t >> 5] = vs;
    __syncthreads();
    if (t == 0) {
        float tot = 0.f;
        for (int j = 0; j < 8; j++) tot += red[j];
        bval = rsqrtf(tot * (1.f / D) + 1e-6f);
    }
    __syncthreads();
    const float rstd = bval;

    float* yr = y + (size_t)row * D;
#pragma unroll
    for (int j = 0; j < 4; j++) {
        const int d = t + j * 256;
        const float sc = mods ? mods[sc_off + d] : 0.f;
        const float sh = mods ? mods[sh_off + d] : 0.f;
        yr[d] = (v[j] - mean) * rstd * (1.f + sc) + sh;
    }
}

// ---------------------------------------------------------------------------
// RoPE (in place, on q and k). One thread per (l, h, pair j<32).
// out_j = x_j*cos_j - x_{j+32}*sin_j ; out_{j+32} = x_{j+32}*cos_{j+32} + x_j*sin_{j+32}
// ---------------------------------------------------------------------------
__global__ void __launch_bounds__(256) rope_kernel(
    float* __restrict__ q, float* __restrict__ k, const float* __restrict__ rope)
{
    const int idx = blockIdx.x * 256 + threadIdx.x;
    if (idx >= L * H * 32) return;
    const int j = idx & 31;
    const int h = (idx >> 5) & 15;
    const int l = idx >> 9;
    const float a1 = rope[l * HD + j];
    const float a2 = rope[l * HD + j + 32];
    const float c1 = cosf(a1), s1 = sinf(a1);
    const float c2 = cosf(a2), s2 = sinf(a2);
    const size_t base = (size_t)l * D + h * HD;

    float q1 = q[base + j], q2 = q[base + j + 32];
    q[base + j]      = q1 * c1 - q2 * s1;
    q[base + j + 32] = q2 * c2 + q1 * s2;

    float k1 = k[base + j], k2 = k[base + j + 32];
    k[base + j]      = k1 * c1 - k2 * s1;
    k[base + j + 32] = k2 * c2 + k1 * s2;
}

// ---------------------------------------------------------------------------
// Flash attention (fp32). Heads in cols h*64..h*64+63 of [Lx, D] tensors.
// Block = (64 queries) x (one head); streams keys in tiles of 32.
// ---------------------------------------------------------------------------
__global__ void __launch_bounds__(256) attn_kernel(
    const float* __restrict__ Q, const float* __restrict__ Kp,
    const float* __restrict__ Vp, float* __restrict__ O,
    int Lk, float scale)
{
    __shared__ float Qs[64][65];
    __shared__ float KVs[32][64];
    __shared__ float Ss[64][33];
    __shared__ float m_s[64], l_s[64], a_s[64];

    const int tid = threadIdx.x;
    const int h   = blockIdx.y;
    const int q0  = blockIdx.x * 64;
    const int ty = tid >> 4, tx = tid & 15;
    const int qa = (tid & 31) * 2;      // 2 query rows for S-phase
    const int ka = (tid >> 5) * 4;      // 4 key cols for S-phase

    for (int i = tid; i < 64 * 64; i += 256) {
        const int r = i >> 6, c = i & 63;
        Qs[r][c] = Q[(size_t)(q0 + r) * D + h * HD + c] * scale;
    }
    if (tid < 64) { m_s[tid] = -1e30f; l_s[tid] = 0.f; }
    float o_acc[4][4] = {};
    __syncthreads();

    for (int kt = 0; kt < Lk; kt += 32) {
        // load K tile
        for (int i = tid; i < 32 * 64; i += 256) {
            const int r = i >> 6, c = i & 63;
            KVs[r][c] = Kp[(size_t)(kt + r) * D + h * HD + c];
        }
        __syncthreads();

        // S = Qs . K^T (each thread: 2 queries x 4 keys)
        float s0[4] = {0, 0, 0, 0}, s1[4] = {0, 0, 0, 0};
#pragma unroll 8
        for (int d = 0; d < 64; d++) {
            const float qv0 = Qs[qa][d], qv1 = Qs[qa + 1][d];
#pragma unroll
            for (int j = 0; j < 4; j++) {
                const float kv = KVs[ka + j][d];
                s0[j] = fmaf(qv0, kv, s0[j]);
                s1[j] = fmaf(qv1, kv, s1[j]);
            }
        }
#pragma unroll
        for (int j = 0; j < 4; j++) {
            Ss[qa][ka + j]     = s0[j];
            Ss[qa + 1][ka + j] = s1[j];
        }
        __syncthreads();

        // online softmax stats (one thread per query row)
        if (tid < 64) {
            const float m_old = m_s[tid];
            float mt = m_old;
#pragma unroll 8
            for (int j = 0; j < 32; j++) mt = fmaxf(mt, Ss[tid][j]);
            const float alpha = expf(m_old - mt);
            float sum = 0.f;
#pragma unroll 8
            for (int j = 0; j < 32; j++) {
                const float p = expf(Ss[tid][j] - mt);
                Ss[tid][j] = p;
                sum += p;
            }
            m_s[tid] = mt;
            a_s[tid] = alpha;
            l_s[tid] = l_s[tid] * alpha + sum;
        }
        __syncthreads();

        // load V tile (reuse KVs)
        for (int i = tid; i < 32 * 64; i += 256) {
            const int r = i >> 6, c = i & 63;
            KVs[r][c] = Vp[(size_t)(kt + r) * D + h * HD + c];
        }
        __syncthreads();

        // rescale accumulators, then O += P . V (each thread 4x4)
#pragma unroll
        for (int i = 0; i < 4; i++) {
            const float al = a_s[ty * 4 + i];
#pragma unroll
            for (int j = 0; j < 4; j++) o_acc[i][j] *= al;
        }
#pragma unroll 4
        for (int kk = 0; kk < 32; kk++) {
            const float4 b4 = *reinterpret_cast<const float4*>(&KVs[kk][tx * 4]);
            const float b[4] = {b4.x, b4.y, b4.z, b4.w};
#pragma unroll
            for (int i = 0; i < 4; i++) {
                const float a = Ss[ty * 4 + i][kk];
#pragma unroll
                for (int j = 0; j < 4; j++)
                    o_acc[i][j] = fmaf(a, b[j], o_acc[i][j]);
            }
        }
        __syncthreads();
    }

#pragma unroll
    for (int i = 0; i < 4; i++) {
        const float inv = 1.f / l_s[ty * 4 + i];
#pragma unroll
        for (int j = 0; j < 4; j++)
            O[(size_t)(q0 + ty * 4 + i) * D + h * HD + tx * 4 + j] = o_acc[i][j] * inv;
    }
}

// ---------------------------------------------------------------------------
extern "C" void kernel_launch(void* const* d_in, const int* in_sizes, int n_in,
                              void* d_out, int out_size)
{
    const float* x_in = (const float*)d_in[0];
    const float* ts   = (const float*)d_in[1];
    const float* ctx  = (const float*)d_in[2];
    const float* rope = (const float*)d_in[3];
    const float* adaW = (const float*)d_in[4];
    const float* adab = (const float*)d_in[5];
    const float* sqW  = (const float*)d_in[6];
    const float* skW  = (const float*)d_in[7];
    const float* svW  = (const float*)d_in[8];
    const float* soW  = (const float*)d_in[9];
    const float* sob  = (const float*)d_in[10];
    const float* cqW  = (const float*)d_in[11];
    const float* ckW  = (const float*)d_in[12];
    const float* cvW  = (const float*)d_in[13];
    const float* coW  = (const float*)d_in[14];
    const float* cob  = (const float*)d_in[15];
    const float* f1W  = (const float*)d_in[16];
    const float* f1b  = (const float*)d_in[17];
    const float* f2W  = (const float*)d_in[18];
    const float* f2b  = (const float*)d_in[19];

    float* x = (float*)d_out;

    float *hx, *q, *k, *v, *o, *ckb, *cvb, *hbuf, *mods;
    cudaGetSymbolAddress((void**)&hx,   g_hx);
    cudaGetSymbolAddress((void**)&q,    g_q);
    cudaGetSymbolAddress((void**)&k,    g_k);
    cudaGetSymbolAddress((void**)&v,    g_v);
    cudaGetSymbolAddress((void**)&o,    g_o);
    cudaGetSymbolAddress((void**)&ckb,  g_ck);
    cudaGetSymbolAddress((void**)&cvb,  g_cv);
    cudaGetSymbolAddress((void**)&hbuf, g_h);
    cudaGetSymbolAddress((void**)&mods, g_mods);

    cudaMemcpyAsync(x, x_in, (size_t)L * D * sizeof(float), cudaMemcpyDeviceToDevice);

    const float scale = 0.125f; // 64^-0.5
    const dim3 gD  (D   / 128, L    / 128);
    const dim3 gDFF(DFF / 128, L    / 128);
    const dim3 gS  (D   / 128, SCTX / 128);
    const dim3 gAtt(L / 64, H);

    for (int i = 0; i < NB; i++) {
        const float* adaW_i = adaW + (size_t)i * 6 * D * D;
        const float* adab_i = adab + (size_t)i * 6 * D;
        const float* sqW_i  = sqW  + (size_t)i * D * D;
        const float* skW_i  = skW  + (size_t)i * D * D;
        const float* svW_i  = svW  + (size_t)i * D * D;
        const float* soW_i  = soW  + (size_t)i * D * D;
        const float* sob_i  = sob  + (size_t)i * D;
        const float* cqW_i  = cqW  + (size_t)i * D * D;
        const float* ckW_i  = ckW  + (size_t)i * D * D;
        const float* cvW_i  = cvW  + (size_t)i * D * D;
        const float* coW_i  = coW  + (size_t)i * D * D;
        const float* cob_i  = cob  + (size_t)i * D;
        const float* f1W_i  = f1W  + (size_t)i * DFF * D;
        const float* f1b_i  = f1b  + (size_t)i * DFF;
        const float* f2W_i  = f2W  + (size_t)i * D * DFF;
        const float* f2b_i  = f2b  + (size_t)i * D;

        // adaLN modulations
        gemv_ada<<<6 * D / 8, 256>>>(ts, adaW_i, adab_i, mods);

        // --- self attention ---
        ln_mod_kernel<<<L, 256>>>(x, mods, 0, D, hx);                 // sh_msa, sc_msa
        gemm_nt<<<gD, 256>>>(hx, sqW_i, nullptr, nullptr, q, L, D, D, EP_STORE);
        gemm_nt<<<gD, 256>>>(hx, skW_i, nullptr, nullptr, k, L, D, D, EP_STORE);
        gemm_nt<<<gD, 256>>>(hx, svW_i, nullptr, nullptr, v, L, D, D, EP_STORE);
        rope_kernel<<<(L * H * 32) / 256, 256>>>(q, k, rope);
        attn_kernel<<<gAtt, 256>>>(q, k, v, o, L, scale);
        gemm_nt<<<gD, 256>>>(o, soW_i, sob_i, mods + 2 * D, x, L, D, D, EP_RESID_GATE);

        // --- cross attention ---
        ln_mod_kernel<<<L, 256>>>(x, nullptr, 0, 0, hx);              // plain LN
        gemm_nt<<<gD, 256>>>(hx,  cqW_i, nullptr, nullptr, q,   L,    D, D, EP_STORE);
        gemm_nt<<<gS, 256>>>(ctx, ckW_i, nullptr, nullptr, ckb, SCTX, D, D, EP_STORE);
        gemm_nt<<<gS, 256>>>(ctx, cvW_i, nullptr, nullptr, cvb, SCTX, D, D, EP_STORE);
        attn_kernel<<<gAtt, 256>>>(q, ckb, cvb, o, SCTX, scale);
        gemm_nt<<<gD, 256>>>(o, coW_i, cob_i, nullptr, x, L, D, D, EP_RESID);

        // --- MLP ---
        ln_mod_kernel<<<L, 256>>>(x, mods, 3 * D, 4 * D, hx);         // sh_mlp, sc_mlp
        gemm_nt<<<gDFF, 256>>>(hx,   f1W_i, f1b_i, nullptr,      hbuf, L, DFF, D,   EP_GELU);
        gemm_nt<<<gD,   256>>>(hbuf, f2W_i, f2b_i, mods + 5 * D, x,    L, D,   DFF, EP_RESID_GATE);
    }
}

// round 2
// speedup vs baseline: 1.4545x; 1.4545x over previous
#include <cuda_runtime.h>
#include <math.h>
#include <stdint.h>

// Problem constants
constexpr int L    = 3072;
constexpr int D    = 1024;
constexpr int H    = 16;
constexpr int HD   = 64;
constexpr int SCTX = 512;
constexpr int DFF  = 4096;
constexpr int NB   = 2;

// ---------------- scratch (static device arrays; no cudaMalloc allowed) ----
__device__ float g_hx[(size_t)L * D];
__device__ float g_q [(size_t)L * D];
__device__ float g_k [(size_t)L * D];
__device__ float g_v [(size_t)L * D];
__device__ float g_o [(size_t)L * D];
__device__ float g_ck[(size_t)SCTX * D];
__device__ float g_cv[(size_t)SCTX * D];
__device__ float g_h [(size_t)L * DFF];
__device__ float g_mods[6 * D];

enum { EP_STORE = 0, EP_GELU = 1, EP_RESID = 2, EP_RESID_GATE = 3 };

__device__ __forceinline__ uint32_t f2tf(float x) {
    uint32_t r;
    asm("cvt.rna.tf32.f32 %0, %1;" : "=r"(r) : "f"(x));
    return r;
}

__device__ __forceinline__ void mma_tf32(float c[4], uint32_t a0, uint32_t a1,
                                         uint32_t a2, uint32_t a3,
                                         uint32_t b0, uint32_t b1) {
    asm volatile(
        "mma.sync.aligned.m16n8k8.row.col.f32.tf32.tf32.f32 "
        "{%0,%1,%2,%3}, {%4,%5,%6,%7}, {%8,%9}, {%0,%1,%2,%3};"
        : "+f"(c[0]), "+f"(c[1]), "+f"(c[2]), "+f"(c[3])
        : "r"(a0), "r"(a1), "r"(a2), "r"(a3), "r"(b0), "r"(b1));
}

// ---------------------------------------------------------------------------
// TF32 tensor-core GEMM: C[M,N] (+epilogue) = A[M,K] (row-major) x W[N,K]^T
// BM=BN=128, BK=16, 256 threads = 8 warps (2 warps M x 4 warps N),
// warp tile 64x32 = 4x4 m16n8k8 mma tiles. Double-buffered smem.
// ---------------------------------------------------------------------------
__global__ void __launch_bounds__(256, 2) gemm_tf32(
    const float* __restrict__ A, const float* __restrict__ W,
    const float* __restrict__ bias, const float* __restrict__ gate,
    float* __restrict__ C, int M, int N, int K, int mode)
{
    // k-major, padded: stride 132 -> fragment loads conflict-free
    __shared__ uint32_t As[2][16][132];
    __shared__ uint32_t Bs[2][16][132];

    const int tid  = threadIdx.x;
    const int m0   = blockIdx.y * 128;
    const int n0   = blockIdx.x * 128;
    const int lane = tid & 31;
    const int warp = tid >> 5;
    const int warpM = warp & 1;   // 0..1 -> 64 rows each
    const int warpN = warp >> 1;  // 0..3 -> 32 cols each
    const int mwb = warpM * 64;
    const int nwb = warpN * 32;
    const int qr = lane >> 2;     // 0..7
    const int qc = lane & 3;      // 0..3

    // loader mapping: each thread owns one row (of 128) and 8 k-values
    const int lrow = tid >> 1;
    const int lk   = (tid & 1) * 8;

    const float* Ap = A + (size_t)(m0 + lrow) * K + lk;
    const float* Wp = W + (size_t)(n0 + lrow) * K + lk;

    float acc[4][4][4];
#pragma unroll
    for (int i = 0; i < 4; i++)
#pragma unroll
        for (int j = 0; j < 4; j++)
#pragma unroll
            for (int e = 0; e < 4; e++) acc[i][j][e] = 0.f;

    const int nT = K >> 4;

    float4 av0, av1, wv0, wv1;

    // prologue: tile 0 -> smem[0]
    av0 = *reinterpret_cast<const float4*>(Ap);
    av1 = *reinterpret_cast<const float4*>(Ap + 4);
    wv0 = *reinterpret_cast<const float4*>(Wp);
    wv1 = *reinterpret_cast<const float4*>(Wp + 4);
    As[0][lk + 0][lrow] = f2tf(av0.x); As[0][lk + 1][lrow] = f2tf(av0.y);
    As[0][lk + 2][lrow] = f2tf(av0.z); As[0][lk + 3][lrow] = f2tf(av0.w);
    As[0][lk + 4][lrow] = f2tf(av1.x); As[0][lk + 5][lrow] = f2tf(av1.y);
    As[0][lk + 6][lrow] = f2tf(av1.z); As[0][lk + 7][lrow] = f2tf(av1.w);
    Bs[0][lk + 0][lrow] = f2tf(wv0.x); Bs[0][lk + 1][lrow] = f2tf(wv0.y);
    Bs[0][lk + 2][lrow] = f2tf(wv0.z); Bs[0][lk + 3][lrow] = f2tf(wv0.w);
    Bs[0][lk + 4][lrow] = f2tf(wv1.x); Bs[0][lk + 5][lrow] = f2tf(wv1.y);
    Bs[0][lk + 6][lrow] = f2tf(wv1.z); Bs[0][lk + 7][lrow] = f2tf(wv1.w);
    __syncthreads();

    for (int t = 0; t < nT; t++) {
        const int buf = t & 1;
        const bool more = (t + 1) < nT;
        if (more) {
            const int k0 = (t + 1) << 4;
            av0 = *reinterpret_cast<const float4*>(Ap + k0);
            av1 = *reinterpret_cast<const float4*>(Ap + k0 + 4);
            wv0 = *reinterpret_cast<const float4*>(Wp + k0);
            wv1 = *reinterpret_cast<const float4*>(Wp + k0 + 4);
        }

#pragma unroll
        for (int ks = 0; ks < 2; ks++) {
            const int kk = ks * 8;
            uint32_t afr[4][4], bfr[4][2];
#pragma unroll
            for (int mt = 0; mt < 4; mt++) {
                const int mb = mwb + mt * 16;
                afr[mt][0] = As[buf][kk + qc    ][mb + qr    ];
                afr[mt][1] = As[buf][kk + qc    ][mb + qr + 8];
                afr[mt][2] = As[buf][kk + qc + 4][mb + qr    ];
                afr[mt][3] = As[buf][kk + qc + 4][mb + qr + 8];
            }
#pragma unroll
            for (int nt = 0; nt < 4; nt++) {
                const int nb = nwb + nt * 8;
                bfr[nt][0] = Bs[buf][kk + qc    ][nb + qr];
                bfr[nt][1] = Bs[buf][kk + qc + 4][nb + qr];
            }
#pragma unroll
            for (int mt = 0; mt < 4; mt++)
#pragma unroll
                for (int nt = 0; nt < 4; nt++)
                    mma_tf32(acc[mt][nt], afr[mt][0], afr[mt][1], afr[mt][2],
                             afr[mt][3], bfr[nt][0], bfr[nt][1]);
        }

        if (more) {
            const int nb2 = buf ^ 1;
            As[nb2][lk + 0][lrow] = f2tf(av0.x); As[nb2][lk + 1][lrow] = f2tf(av0.y);
            As[nb2][lk + 2][lrow] = f2tf(av0.z); As[nb2][lk + 3][lrow] = f2tf(av0.w);
            As[nb2][lk + 4][lrow] = f2tf(av1.x); As[nb2][lk + 5][lrow] = f2tf(av1.y);
            As[nb2][lk + 6][lrow] = f2tf(av1.z); As[nb2][lk + 7][lrow] = f2tf(av1.w);
            Bs[nb2][lk + 0][lrow] = f2tf(wv0.x); Bs[nb2][lk + 1][lrow] = f2tf(wv0.y);
            Bs[nb2][lk + 2][lrow] = f2tf(wv0.z); Bs[nb2][lk + 3][lrow] = f2tf(wv0.w);
            Bs[nb2][lk + 4][lrow] = f2tf(wv1.x); Bs[nb2][lk + 5][lrow] = f2tf(wv1.y);
            Bs[nb2][lk + 6][lrow] = f2tf(wv1.z); Bs[nb2][lk + 7][lrow] = f2tf(wv1.w);
            __syncthreads();
        }
    }

    // epilogue: fragment layout m16n8 -> rows qr,qr+8; cols 2*qc, 2*qc+1
#pragma unroll
    for (int mt = 0; mt < 4; mt++) {
#pragma unroll
        for (int nt = 0; nt < 4; nt++) {
#pragma unroll
            for (int half = 0; half < 2; half++) {
                const int r = m0 + mwb + mt * 16 + qr + half * 8;
#pragma unroll
                for (int e = 0; e < 2; e++) {
                    const int c = n0 + nwb + nt * 8 + 2 * qc + e;
                    float val = acc[mt][nt][half * 2 + e];
                    val += bias ? bias[c] : 0.f;
                    float* Cp = C + (size_t)r * N + c;
                    if (mode == EP_STORE) {
                        *Cp = val;
                    } else if (mode == EP_GELU) {
                        *Cp = 0.5f * val * (1.f + erff(val * 0.70710678118654752f));
                    } else if (mode == EP_RESID) {
                        *Cp += val;
                    } else { // EP_RESID_GATE
                        *Cp += gate[c] * val;
                    }
                }
            }
        }
    }
}

// ---------------------------------------------------------------------------
// adaLN modulation GEMV: out[6D] = t[D] @ W[6D,D]^T + b  (warp per output)
// ---------------------------------------------------------------------------
__global__ void __launch_bounds__(256) gemv_ada(
    const float* __restrict__ t, const float* __restrict__ Wt,
    const float* __restrict__ b, float* __restrict__ out)
{
    const int o    = blockIdx.x * 8 + (threadIdx.x >> 5);
    const int lane = threadIdx.x & 31;
    const float* wr = Wt + (size_t)o * D;
    float s = 0.f;
    for (int d = lane; d < D; d += 32) s = fmaf(t[d], wr[d], s);
#pragma unroll
    for (int off = 16; off; off >>= 1) s += __shfl_xor_sync(0xffffffffu, s, off);
    if (lane == 0) out[o] = s + b[o];
}

// ---------------------------------------------------------------------------
// LayerNorm (+ optional adaLN shift/scale): y = LN(x)*(1+sc)+sh
// ---------------------------------------------------------------------------
__global__ void __launch_bounds__(256) ln_mod_kernel(
    const float* __restrict__ x, const float* __restrict__ mods,
    int sh_off, int sc_off, float* __restrict__ y)
{
    __shared__ float red[8];
    __shared__ float bval;
    const int row = blockIdx.x;
    const int t = threadIdx.x;
    const float* xr = x + (size_t)row * D;

    float v[4];
    float s = 0.f;
#pragma unroll
    for (int j = 0; j < 4; j++) { v[j] = xr[t + j * 256]; s += v[j]; }
#pragma unroll
    for (int off = 16; off; off >>= 1) s += __shfl_xor_sync(0xffffffffu, s, off);
    if ((t & 31) == 0) red[t >> 5] = s;
    __syncthreads();
    if (t == 0) {
        float tot = 0.f;
        for (int j = 0; j < 8; j++) tot += red[j];
        bval = tot * (1.f / D);
    }
    __syncthreads();
    const float mean = bval;

    float vs = 0.f;
#pragma unroll
    for (int j = 0; j < 4; j++) { float d = v[j] - mean; vs = fmaf(d, d, vs); }
#pragma unroll
    for (int off = 16; off; off >>= 1) vs += __shfl_xor_sync(0xffffffffu, vs, off);
    if ((t & 31) == 0) red[t >> 5] = vs;
    __syncthreads();
    if (t == 0) {
        float tot = 0.f;
        for (int j = 0; j < 8; j++) tot += red[j];
        bval = rsqrtf(tot * (1.f / D) + 1e-6f);
    }
    __syncthreads();
    const float rstd = bval;

    float* yr = y + (size_t)row * D;
#pragma unroll
    for (int j = 0; j < 4; j++) {
        const int d = t + j * 256;
        const float sc = mods ? mods[sc_off + d] : 0.f;
        const float sh = mods ? mods[sh_off + d] : 0.f;
        yr[d] = (v[j] - mean) * rstd * (1.f + sc) + sh;
    }
}

// ---------------------------------------------------------------------------
// RoPE (in place, on q and k).
// ---------------------------------------------------------------------------
__global__ void __launch_bounds__(256) rope_kernel(
    float* __restrict__ q, float* __restrict__ k, const float* __restrict__ rope)
{
    const int idx = blockIdx.x * 256 + threadIdx.x;
    if (idx >= L * H * 32) return;
    const int j = idx & 31;
    const int h = (idx >> 5) & 15;
    const int l = idx >> 9;
    const float a1 = rope[l * HD + j];
    const float a2 = rope[l * HD + j + 32];
    const float c1 = cosf(a1), s1 = sinf(a1);
    const float c2 = cosf(a2), s2 = sinf(a2);
    const size_t base = (size_t)l * D + h * HD;

    float q1 = q[base + j], q2 = q[base + j + 32];
    q[base + j]      = q1 * c1 - q2 * s1;
    q[base + j + 32] = q2 * c2 + q1 * s2;

    float k1 = k[base + j], k2 = k[base + j + 32];
    k[base + j]      = k1 * c1 - k2 * s1;
    k[base + j + 32] = k2 * c2 + k1 * s2;
}

// ---------------------------------------------------------------------------
// Flash attention (fp32 SIMT — unchanged this round).
// ---------------------------------------------------------------------------
__global__ void __launch_bounds__(256) attn_kernel(
    const float* __restrict__ Q, const float* __restrict__ Kp,
    const float* __restrict__ Vp, float* __restrict__ O,
    int Lk, float scale)
{
    __shared__ float Qs[64][65];
    __shared__ float KVs[32][64];
    __shared__ float Ss[64][33];
    __shared__ float m_s[64], l_s[64], a_s[64];

    const int tid = threadIdx.x;
    const int h   = blockIdx.y;
    const int q0  = blockIdx.x * 64;
    const int ty = tid >> 4, tx = tid & 15;
    const int qa = (tid & 31) * 2;
    const int ka = (tid >> 5) * 4;

    for (int i = tid; i < 64 * 64; i += 256) {
        const int r = i >> 6, c = i & 63;
        Qs[r][c] = Q[(size_t)(q0 + r) * D + h * HD + c] * scale;
    }
    if (tid < 64) { m_s[tid] = -1e30f; l_s[tid] = 0.f; }
    float o_acc[4][4] = {};
    __syncthreads();

    for (int kt = 0; kt < Lk; kt += 32) {
        for (int i = tid; i < 32 * 64; i += 256) {
            const int r = i >> 6, c = i & 63;
            KVs[r][c] = Kp[(size_t)(kt + r) * D + h * HD + c];
        }
        __syncthreads();

        float s0[4] = {0, 0, 0, 0}, s1[4] = {0, 0, 0, 0};
#pragma unroll 8
        for (int d = 0; d < 64; d++) {
            const float qv0 = Qs[qa][d], qv1 = Qs[qa + 1][d];
#pragma unroll
            for (int j = 0; j < 4; j++) {
                const float kv = KVs[ka + j][d];
                s0[j] = fmaf(qv0, kv, s0[j]);
                s1[j] = fmaf(qv1, kv, s1[j]);
            }
        }
#pragma unroll
        for (int j = 0; j < 4; j++) {
            Ss[qa][ka + j]     = s0[j];
            Ss[qa + 1][ka + j] = s1[j];
        }
        __syncthreads();

        if (tid < 64) {
            const float m_old = m_s[tid];
            float mt = m_old;
#pragma unroll 8
            for (int j = 0; j < 32; j++) mt = fmaxf(mt, Ss[tid][j]);
            const float alpha = expf(m_old - mt);
            float sum = 0.f;
#pragma unroll 8
            for (int j = 0; j < 32; j++) {
                const float p = expf(Ss[tid][j] - mt);
                Ss[tid][j] = p;
                sum += p;
            }
            m_s[tid] = mt;
            a_s[tid] = alpha;
            l_s[tid] = l_s[tid] * alpha + sum;
        }
        __syncthreads();

        for (int i = tid; i < 32 * 64; i += 256) {
            const int r = i >> 6, c = i & 63;
            KVs[r][c] = Vp[(size_t)(kt + r) * D + h * HD + c];
        }
        __syncthreads();

#pragma unroll
        for (int i = 0; i < 4; i++) {
            const float al = a_s[ty * 4 + i];
#pragma unroll
            for (int j = 0; j < 4; j++) o_acc[i][j] *= al;
        }
#pragma unroll 4
        for (int kk = 0; kk < 32; kk++) {
            const float4 b4 = *reinterpret_cast<const float4*>(&KVs[kk][tx * 4]);
            const float b[4] = {b4.x, b4.y, b4.z, b4.w};
#pragma unroll
            for (int i = 0; i < 4; i++) {
                const float a = Ss[ty * 4 + i][kk];
#pragma unroll
                for (int j = 0; j < 4; j++)
                    o_acc[i][j] = fmaf(a, b[j], o_acc[i][j]);
            }
        }
        __syncthreads();
    }

#pragma unroll
    for (int i = 0; i < 4; i++) {
        const float inv = 1.f / l_s[ty * 4 + i];
#pragma unroll
        for (int j = 0; j < 4; j++)
            O[(size_t)(q0 + ty * 4 + i) * D + h * HD + tx * 4 + j] = o_acc[i][j] * inv;
    }
}

// ---------------------------------------------------------------------------
extern "C" void kernel_launch(void* const* d_in, const int* in_sizes, int n_in,
                              void* d_out, int out_size)
{
    const float* x_in = (const float*)d_in[0];
    const float* ts   = (const float*)d_in[1];
    const float* ctx  = (const float*)d_in[2];
    const float* rope = (const float*)d_in[3];
    const float* adaW = (const float*)d_in[4];
    const float* adab = (const float*)d_in[5];
    const float* sqW  = (const float*)d_in[6];
    const float* skW  = (const float*)d_in[7];
    const float* svW  = (const float*)d_in[8];
    const float* soW  = (const float*)d_in[9];
    const float* sob  = (const float*)d_in[10];
    const float* cqW  = (const float*)d_in[11];
    const float* ckW  = (const float*)d_in[12];
    const float* cvW  = (const float*)d_in[13];
    const float* coW  = (const float*)d_in[14];
    const float* cob  = (const float*)d_in[15];
    const float* f1W  = (const float*)d_in[16];
    const float* f1b  = (const float*)d_in[17];
    const float* f2W  = (const float*)d_in[18];
    const float* f2b  = (const float*)d_in[19];

    float* x = (float*)d_out;

    float *hx, *q, *k, *v, *o, *ckb, *cvb, *hbuf, *mods;
    cudaGetSymbolAddress((void**)&hx,   g_hx);
    cudaGetSymbolAddress((void**)&q,    g_q);
    cudaGetSymbolAddress((void**)&k,    g_k);
    cudaGetSymbolAddress((void**)&v,    g_v);
    cudaGetSymbolAddress((void**)&o,    g_o);
    cudaGetSymbolAddress((void**)&ckb,  g_ck);
    cudaGetSymbolAddress((void**)&cvb,  g_cv);
    cudaGetSymbolAddress((void**)&hbuf, g_h);
    cudaGetSymbolAddress((void**)&mods, g_mods);

    cudaMemcpyAsync(x, x_in, (size_t)L * D * sizeof(float), cudaMemcpyDeviceToDevice);

    const float scale = 0.125f; // 64^-0.5
    const dim3 gD  (D   / 128, L    / 128);
    const dim3 gDFF(DFF / 128, L    / 128);
    const dim3 gS  (D   / 128, SCTX / 128);
    const dim3 gAtt(L / 64, H);

    for (int i = 0; i < NB; i++) {
        const float* adaW_i = adaW + (size_t)i * 6 * D * D;
        const float* adab_i = adab + (size_t)i * 6 * D;
        const float* sqW_i  = sqW  + (size_t)i * D * D;
        const float* skW_i  = skW  + (size_t)i * D * D;
        const float* svW_i  = svW  + (size_t)i * D * D;
        const float* soW_i  = soW  + (size_t)i * D * D;
        const float* sob_i  = sob  + (size_t)i * D;
        const float* cqW_i  = cqW  + (size_t)i * D * D;
        const float* ckW_i  = ckW  + (size_t)i * D * D;
        const float* cvW_i  = cvW  + (size_t)i * D * D;
        const float* coW_i  = coW  + (size_t)i * D * D;
        const float* cob_i  = cob  + (size_t)i * D;
        const float* f1W_i  = f1W  + (size_t)i * DFF * D;
        const float* f1b_i  = f1b  + (size_t)i * DFF;
        const float* f2W_i  = f2W  + (size_t)i * D * DFF;
        const float* f2b_i  = f2b  + (size_t)i * D;

        // adaLN modulations
        gemv_ada<<<6 * D / 8, 256>>>(ts, adaW_i, adab_i, mods);

        // --- self attention ---
        ln_mod_kernel<<<L, 256>>>(x, mods, 0, D, hx);
        gemm_tf32<<<gD, 256>>>(hx, sqW_i, nullptr, nullptr, q, L, D, D, EP_STORE);
        gemm_tf32<<<gD, 256>>>(hx, skW_i, nullptr, nullptr, k, L, D, D, EP_STORE);
        gemm_tf32<<<gD, 256>>>(hx, svW_i, nullptr, nullptr, v, L, D, D, EP_STORE);
        rope_kernel<<<(L * H * 32) / 256, 256>>>(q, k, rope);
        attn_kernel<<<gAtt, 256>>>(q, k, v, o, L, scale);
        gemm_tf32<<<gD, 256>>>(o, soW_i, sob_i, mods + 2 * D, x, L, D, D, EP_RESID_GATE);

        // --- cross attention ---
        ln_mod_kernel<<<L, 256>>>(x, nullptr, 0, 0, hx);
        gemm_tf32<<<gD, 256>>>(hx,  cqW_i, nullptr, nullptr, q,   L,    D, D, EP_STORE);
        gemm_tf32<<<gS, 256>>>(ctx, ckW_i, nullptr, nullptr, ckb, SCTX, D, D, EP_STORE);
        gemm_tf32<<<gS, 256>>>(ctx, cvW_i, nullptr, nullptr, cvb, SCTX, D, D, EP_STORE);
        attn_kernel<<<gAtt, 256>>>(q, ckb, cvb, o, SCTX, scale);
        gemm_tf32<<<gD, 256>>>(o, coW_i, cob_i, nullptr, x, L, D, D, EP_RESID);

        // --- MLP ---
        ln_mod_kernel<<<L, 256>>>(x, mods, 3 * D, 4 * D, hx);
        gemm_tf32<<<gDFF, 256>>>(hx,   f1W_i, f1b_i, nullptr,      hbuf, L, DFF, D,   EP_GELU);
        gemm_tf32<<<gD,   256>>>(hbuf, f2W_i, f2b_i, mods + 5 * D, x,    L, D,   DFF, EP_RESID_GATE);
    }
}

// round 3
// speedup vs baseline: 2.2867x; 1.5722x over previous
#include <cuda_runtime.h>
#include <math.h>
#include <stdint.h>

// Problem constants
constexpr int L    = 3072;
constexpr int D    = 1024;
constexpr int H    = 16;
constexpr int HD   = 64;
constexpr int SCTX = 512;
constexpr int DFF  = 4096;
constexpr int NB   = 2;

// ---------------- scratch (static device arrays; no cudaMalloc allowed) ----
__device__ float g_hx[(size_t)L * D];
__device__ float g_q [(size_t)L * D];
__device__ float g_k [(size_t)L * D];
__device__ float g_v [(size_t)L * D];
__device__ float g_o [(size_t)L * D];
__device__ float g_ck[(size_t)SCTX * D];
__device__ float g_cv[(size_t)SCTX * D];
__device__ float g_h [(size_t)L * DFF];
__device__ float g_kt[(size_t)H * HD * L];   // K^T [h][d][l]
__device__ float g_mods[6 * D];

enum { EP_STORE = 0, EP_GELU = 1, EP_RESID = 2, EP_RESID_GATE = 3 };

__device__ __forceinline__ uint32_t f2tf(float x) {
    uint32_t r;
    asm("cvt.rna.tf32.f32 %0, %1;" : "=r"(r) : "f"(x));
    return r;
}

__device__ __forceinline__ void mma_tf32(float c[4], uint32_t a0, uint32_t a1,
                                         uint32_t a2, uint32_t a3,
                                         uint32_t b0, uint32_t b1) {
    asm volatile(
        "mma.sync.aligned.m16n8k8.row.col.f32.tf32.tf32.f32 "
        "{%0,%1,%2,%3}, {%4,%5,%6,%7}, {%8,%9}, {%0,%1,%2,%3};"
        : "+f"(c[0]), "+f"(c[1]), "+f"(c[2]), "+f"(c[3])
        : "r"(a0), "r"(a1), "r"(a2), "r"(a3), "r"(b0), "r"(b1));
}

// ---------------------------------------------------------------------------
// TF32 tensor-core GEMM (unchanged from R2)
// ---------------------------------------------------------------------------
__global__ void __launch_bounds__(256, 2) gemm_tf32(
    const float* __restrict__ A, const float* __restrict__ W,
    const float* __restrict__ bias, const float* __restrict__ gate,
    float* __restrict__ C, int M, int N, int K, int mode)
{
    __shared__ uint32_t As[2][16][132];
    __shared__ uint32_t Bs[2][16][132];

    const int tid  = threadIdx.x;
    const int m0   = blockIdx.y * 128;
    const int n0   = blockIdx.x * 128;
    const int lane = tid & 31;
    const int warp = tid >> 5;
    const int warpM = warp & 1;
    const int warpN = warp >> 1;
    const int mwb = warpM * 64;
    const int nwb = warpN * 32;
    const int qr = lane >> 2;
    const int qc = lane & 3;

    const int lrow = tid >> 1;
    const int lk   = (tid & 1) * 8;

    const float* Ap = A + (size_t)(m0 + lrow) * K + lk;
    const float* Wp = W + (size_t)(n0 + lrow) * K + lk;

    float acc[4][4][4];
#pragma unroll
    for (int i = 0; i < 4; i++)
#pragma unroll
        for (int j = 0; j < 4; j++)
#pragma unroll
            for (int e = 0; e < 4; e++) acc[i][j][e] = 0.f;

    const int nT = K >> 4;

    float4 av0, av1, wv0, wv1;

    av0 = *reinterpret_cast<const float4*>(Ap);
    av1 = *reinterpret_cast<const float4*>(Ap + 4);
    wv0 = *reinterpret_cast<const float4*>(Wp);
    wv1 = *reinterpret_cast<const float4*>(Wp + 4);
    As[0][lk + 0][lrow] = f2tf(av0.x); As[0][lk + 1][lrow] = f2tf(av0.y);
    As[0][lk + 2][lrow] = f2tf(av0.z); As[0][lk + 3][lrow] = f2tf(av0.w);
    As[0][lk + 4][lrow] = f2tf(av1.x); As[0][lk + 5][lrow] = f2tf(av1.y);
    As[0][lk + 6][lrow] = f2tf(av1.z); As[0][lk + 7][lrow] = f2tf(av1.w);
    Bs[0][lk + 0][lrow] = f2tf(wv0.x); Bs[0][lk + 1][lrow] = f2tf(wv0.y);
    Bs[0][lk + 2][lrow] = f2tf(wv0.z); Bs[0][lk + 3][lrow] = f2tf(wv0.w);
    Bs[0][lk + 4][lrow] = f2tf(wv1.x); Bs[0][lk + 5][lrow] = f2tf(wv1.y);
    Bs[0][lk + 6][lrow] = f2tf(wv1.z); Bs[0][lk + 7][lrow] = f2tf(wv1.w);
    __syncthreads();

    for (int t = 0; t < nT; t++) {
        const int buf = t & 1;
        const bool more = (t + 1) < nT;
        if (more) {
            const int k0 = (t + 1) << 4;
            av0 = *reinterpret_cast<const float4*>(Ap + k0);
            av1 = *reinterpret_cast<const float4*>(Ap + k0 + 4);
            wv0 = *reinterpret_cast<const float4*>(Wp + k0);
            wv1 = *reinterpret_cast<const float4*>(Wp + k0 + 4);
        }

#pragma unroll
        for (int ks = 0; ks < 2; ks++) {
            const int kk = ks * 8;
            uint32_t afr[4][4], bfr[4][2];
#pragma unroll
            for (int mt = 0; mt < 4; mt++) {
                const int mb = mwb + mt * 16;
                afr[mt][0] = As[buf][kk + qc    ][mb + qr    ];
                afr[mt][1] = As[buf][kk + qc    ][mb + qr + 8];
                afr[mt][2] = As[buf][kk + qc + 4][mb + qr    ];
                afr[mt][3] = As[buf][kk + qc + 4][mb + qr + 8];
            }
#pragma unroll
            for (int nt = 0; nt < 4; nt++) {
                const int nb = nwb + nt * 8;
                bfr[nt][0] = Bs[buf][kk + qc    ][nb + qr];
                bfr[nt][1] = Bs[buf][kk + qc + 4][nb + qr];
            }
#pragma unroll
            for (int mt = 0; mt < 4; mt++)
#pragma unroll
                for (int nt = 0; nt < 4; nt++)
                    mma_tf32(acc[mt][nt], afr[mt][0], afr[mt][1], afr[mt][2],
                             afr[mt][3], bfr[nt][0], bfr[nt][1]);
        }

        if (more) {
            const int nb2 = buf ^ 1;
            As[nb2][lk + 0][lrow] = f2tf(av0.x); As[nb2][lk + 1][lrow] = f2tf(av0.y);
            As[nb2][lk + 2][lrow] = f2tf(av0.z); As[nb2][lk + 3][lrow] = f2tf(av0.w);
            As[nb2][lk + 4][lrow] = f2tf(av1.x); As[nb2][lk + 5][lrow] = f2tf(av1.y);
            As[nb2][lk + 6][lrow] = f2tf(av1.z); As[nb2][lk + 7][lrow] = f2tf(av1.w);
            Bs[nb2][lk + 0][lrow] = f2tf(wv0.x); Bs[nb2][lk + 1][lrow] = f2tf(wv0.y);
            Bs[nb2][lk + 2][lrow] = f2tf(wv0.z); Bs[nb2][lk + 3][lrow] = f2tf(wv0.w);
            Bs[nb2][lk + 4][lrow] = f2tf(wv1.x); Bs[nb2][lk + 5][lrow] = f2tf(wv1.y);
            Bs[nb2][lk + 6][lrow] = f2tf(wv1.z); Bs[nb2][lk + 7][lrow] = f2tf(wv1.w);
            __syncthreads();
        }
    }

#pragma unroll
    for (int mt = 0; mt < 4; mt++) {
#pragma unroll
        for (int nt = 0; nt < 4; nt++) {
#pragma unroll
            for (int half = 0; half < 2; half++) {
                const int r = m0 + mwb + mt * 16 + qr + half * 8;
#pragma unroll
                for (int e = 0; e < 2; e++) {
                    const int c = n0 + nwb + nt * 8 + 2 * qc + e;
                    float val = acc[mt][nt][half * 2 + e];
                    val += bias ? bias[c] : 0.f;
                    float* Cp = C + (size_t)r * N + c;
                    if (mode == EP_STORE) {
                        *Cp = val;
                    } else if (mode == EP_GELU) {
                        *Cp = 0.5f * val * (1.f + erff(val * 0.70710678118654752f));
                    } else if (mode == EP_RESID) {
                        *Cp += val;
                    } else {
                        *Cp += gate[c] * val;
                    }
                }
            }
        }
    }
}

// ---------------------------------------------------------------------------
// adaLN modulation GEMV
// ---------------------------------------------------------------------------
__global__ void __launch_bounds__(256) gemv_ada(
    const float* __restrict__ t, const float* __restrict__ Wt,
    const float* __restrict__ b, float* __restrict__ out)
{
    const int o    = blockIdx.x * 8 + (threadIdx.x >> 5);
    const int lane = threadIdx.x & 31;
    const float* wr = Wt + (size_t)o * D;
    float s = 0.f;
    for (int d = lane; d < D; d += 32) s = fmaf(t[d], wr[d], s);
#pragma unroll
    for (int off = 16; off; off >>= 1) s += __shfl_xor_sync(0xffffffffu, s, off);
    if (lane == 0) out[o] = s + b[o];
}

// ---------------------------------------------------------------------------
// LayerNorm (+ optional adaLN shift/scale)
// ---------------------------------------------------------------------------
__global__ void __launch_bounds__(256) ln_mod_kernel(
    const float* __restrict__ x, const float* __restrict__ mods,
    int sh_off, int sc_off, float* __restrict__ y)
{
    __shared__ float red[8];
    __shared__ float bval;
    const int row = blockIdx.x;
    const int t = threadIdx.x;
    const float* xr = x + (size_t)row * D;

    float v[4];
    float s = 0.f;
#pragma unroll
    for (int j = 0; j < 4; j++) { v[j] = xr[t + j * 256]; s += v[j]; }
#pragma unroll
    for (int off = 16; off; off >>= 1) s += __shfl_xor_sync(0xffffffffu, s, off);
    if ((t & 31) == 0) red[t >> 5] = s;
    __syncthreads();
    if (t == 0) {
        float tot = 0.f;
        for (int j = 0; j < 8; j++) tot += red[j];
        bval = tot * (1.f / D);
    }
    __syncthreads();
    const float mean = bval;

    float vs = 0.f;
#pragma unroll
    for (int j = 0; j < 4; j++) { float d = v[j] - mean; vs = fmaf(d, d, vs); }
#pragma unroll
    for (int off = 16; off; off >>= 1) vs += __shfl_xor_sync(0xffffffffu, vs, off);
    if ((t & 31) == 0) red[t >> 5] = vs;
    __syncthreads();
    if (t == 0) {
        float tot = 0.f;
        for (int j = 0; j < 8; j++) tot += red[j];
        bval = rsqrtf(tot * (1.f / D) + 1e-6f);
    }
    __syncthreads();
    const float rstd = bval;

    float* yr = y + (size_t)row * D;
#pragma unroll
    for (int j = 0; j < 4; j++) {
        const int d = t + j * 256;
        const float sc = mods ? mods[sc_off + d] : 0.f;
        const float sh = mods ? mods[sh_off + d] : 0.f;
        yr[d] = (v[j] - mean) * rstd * (1.f + sc) + sh;
    }
}

// ---------------------------------------------------------------------------
// RoPE (in place, on q and k)
// ---------------------------------------------------------------------------
__global__ void __launch_bounds__(256) rope_kernel(
    float* __restrict__ q, float* __restrict__ k, const float* __restrict__ rope)
{
    const int idx = blockIdx.x * 256 + threadIdx.x;
    if (idx >= L * H * 32) return;
    const int j = idx & 31;
    const int h = (idx >> 5) & 15;
    const int l = idx >> 9;
    const float a1 = rope[l * HD + j];
    const float a2 = rope[l * HD + j + 32];
    const float c1 = cosf(a1), s1 = sinf(a1);
    const float c2 = cosf(a2), s2 = sinf(a2);
    const size_t base = (size_t)l * D + h * HD;

    float q1 = q[base + j], q2 = q[base + j + 32];
    q[base + j]      = q1 * c1 - q2 * s1;
    q[base + j + 32] = q2 * c2 + q1 * s2;

    float k1 = k[base + j], k2 = k[base + j + 32];
    k[base + j]      = k1 * c1 - k2 * s1;
    k[base + j + 32] = k2 * c2 + k1 * s2;
}

// ---------------------------------------------------------------------------
// K transpose: Kin [Lk rows x D cols (head h at cols h*64..)] -> KT [h][d][l]
// Values pre-rounded to tf32. Block (32,8), tile 32x32.
// ---------------------------------------------------------------------------
__global__ void __launch_bounds__(256) transpose_k(
    const float* __restrict__ Kin, float* __restrict__ KT, int Lk)
{
    __shared__ float t[32][33];
    const int h  = blockIdx.z;
    const int d0 = blockIdx.y * 32;
    const int l0 = blockIdx.x * 32;
    const int tx = threadIdx.x, ty = threadIdx.y;
#pragma unroll
    for (int j = 0; j < 4; j++)
        t[ty + j * 8][tx] = Kin[(size_t)(l0 + ty + j * 8) * D + h * HD + d0 + tx];
    __syncthreads();
#pragma unroll
    for (int j = 0; j < 4; j++)
        KT[(size_t)h * HD * Lk + (size_t)(d0 + ty + j * 8) * Lk + l0 + tx] =
            __uint_as_float(f2tf(t[tx][ty + j * 8]));
}

// ---------------------------------------------------------------------------
// Tensor-core flash attention (tf32).
// Block: 64 queries x 1 head, 4 warps (16 rows each). KV tiles of 64.
// KT is pre-transposed+tf32 [h][d][l]. Smem strides: Ks/Vs 72 (=8 mod 32,
// conflict-free B-frag LDS), Ps 68 (=4 mod 32, conflict-free A-frag LDS).
// ---------------------------------------------------------------------------
__global__ void __launch_bounds__(128) attn_mma(
    const float* __restrict__ Q, const float* __restrict__ KT,
    const float* __restrict__ Vp, float* __restrict__ O,
    int Lk, float scale)
{
    extern __shared__ float sm[];
    float* Ks = sm;                  // [64][72]
    float* Vs = sm + 64 * 72;        // [64][72]
    float* Ps = sm + 2 * 64 * 72;    // [64][68]  (Q staging, then P)

    const int tid  = threadIdx.x;
    const int warp = tid >> 5;
    const int lane = tid & 31;
    const int qr = lane >> 2, qc = lane & 3;
    const int h  = blockIdx.y;
    const int q0 = blockIdx.x * 64;
    const int row0 = warp * 16;

    // stage Q (scaled) into Ps
    for (int i = tid; i < 64 * 16; i += 128) {
        const int r = i >> 4, c4 = (i & 15) * 4;
        float4 qv = *reinterpret_cast<const float4*>(&Q[(size_t)(q0 + r) * D + h * HD + c4]);
        float* dst = &Ps[r * 68 + c4];
        dst[0] = qv.x * scale; dst[1] = qv.y * scale;
        dst[2] = qv.z * scale; dst[3] = qv.w * scale;
    }
    __syncthreads();

    // Q fragments in registers for the whole kernel
    uint32_t qf[8][4];
#pragma unroll
    for (int ks = 0; ks < 8; ks++) {
        const int kk = ks * 8;
        qf[ks][0] = f2tf(Ps[(row0 + qr    ) * 68 + kk + qc    ]);
        qf[ks][1] = f2tf(Ps[(row0 + qr + 8) * 68 + kk + qc    ]);
        qf[ks][2] = f2tf(Ps[(row0 + qr    ) * 68 + kk + qc + 4]);
        qf[ks][3] = f2tf(Ps[(row0 + qr + 8) * 68 + kk + qc + 4]);
    }

    float m0 = -1e30f, m1 = -1e30f, l0 = 0.f, l1 = 0.f;
    float oacc[8][4];
#pragma unroll
    for (int nt = 0; nt < 8; nt++)
#pragma unroll
        for (int e = 0; e < 4; e++) oacc[nt][e] = 0.f;

    const float* KTh = KT + (size_t)h * HD * Lk;

    for (int kt = 0; kt < Lk; kt += 64) {
        __syncthreads();  // prev-iter Ks/Vs reads (and Q-frag reads) done
        // load K^T tile (already tf32) and V tile (round here)
        for (int i = tid; i < 64 * 16; i += 128) {
            const int r = i >> 4, c4 = (i & 15) * 4;
            float4 kv = *reinterpret_cast<const float4*>(&KTh[(size_t)r * Lk + kt + c4]);
            *reinterpret_cast<float4*>(&Ks[r * 72 + c4]) = kv;
            float4 vv = *reinterpret_cast<const float4*>(&Vp[(size_t)(kt + r) * D + h * HD + c4]);
            float4 vr;
            vr.x = __uint_as_float(f2tf(vv.x));
            vr.y = __uint_as_float(f2tf(vv.y));
            vr.z = __uint_as_float(f2tf(vv.z));
            vr.w = __uint_as_float(f2tf(vv.w));
            *reinterpret_cast<float4*>(&Vs[r * 72 + c4]) = vr;
        }
        __syncthreads();

        // S = Q K^T
        float sf[8][4];
#pragma unroll
        for (int nt = 0; nt < 8; nt++)
#pragma unroll
            for (int e = 0; e < 4; e++) sf[nt][e] = 0.f;
#pragma unroll
        for (int ks = 0; ks < 8; ks++) {
            const int kk = ks * 8;
#pragma unroll
            for (int nt = 0; nt < 8; nt++) {
                const uint32_t b0 = __float_as_uint(Ks[(kk + qc    ) * 72 + nt * 8 + qr]);
                const uint32_t b1 = __float_as_uint(Ks[(kk + qc + 4) * 72 + nt * 8 + qr]);
                mma_tf32(sf[nt], qf[ks][0], qf[ks][1], qf[ks][2], qf[ks][3], b0, b1);
            }
        }

        // online softmax (rows qr and qr+8; stats shared across qc-lane group)
        float rmax0 = -1e30f, rmax1 = -1e30f;
#pragma unroll
        for (int nt = 0; nt < 8; nt++) {
            rmax0 = fmaxf(rmax0, fmaxf(sf[nt][0], sf[nt][1]));
            rmax1 = fmaxf(rmax1, fmaxf(sf[nt][2], sf[nt][3]));
        }
        rmax0 = fmaxf(rmax0, __shfl_xor_sync(0xffffffffu, rmax0, 1));
        rmax0 = fmaxf(rmax0, __shfl_xor_sync(0xffffffffu, rmax0, 2));
        rmax1 = fmaxf(rmax1, __shfl_xor_sync(0xffffffffu, rmax1, 1));
        rmax1 = fmaxf(rmax1, __shfl_xor_sync(0xffffffffu, rmax1, 2));

        const float mn0 = fmaxf(m0, rmax0);
        const float mn1 = fmaxf(m1, rmax1);
        const float a0 = __expf(m0 - mn0);
        const float a1 = __expf(m1 - mn1);
        float rs0 = 0.f, rs1 = 0.f;
#pragma unroll
        for (int nt = 0; nt < 8; nt++) {
            sf[nt][0] = __expf(sf[nt][0] - mn0);
            sf[nt][1] = __expf(sf[nt][1] - mn0);
            sf[nt][2] = __expf(sf[nt][2] - mn1);
            sf[nt][3] = __expf(sf[nt][3] - mn1);
            rs0 += sf[nt][0] + sf[nt][1];
            rs1 += sf[nt][2] + sf[nt][3];
        }
        rs0 += __shfl_xor_sync(0xffffffffu, rs0, 1);
        rs0 += __shfl_xor_sync(0xffffffffu, rs0, 2);
        rs1 += __shfl_xor_sync(0xffffffffu, rs1, 1);
        rs1 += __shfl_xor_sync(0xffffffffu, rs1, 2);
        l0 = l0 * a0 + rs0;
        l1 = l1 * a1 + rs1;
        m0 = mn0; m1 = mn1;
#pragma unroll
        for (int nt = 0; nt < 8; nt++) {
            oacc[nt][0] *= a0; oacc[nt][1] *= a0;
            oacc[nt][2] *= a1; oacc[nt][3] *= a1;
        }

        // store P (rounded) into warp-private Ps rows
        __syncwarp();
#pragma unroll
        for (int nt = 0; nt < 8; nt++) {
            float2 p0 = make_float2(__uint_as_float(f2tf(sf[nt][0])),
                                    __uint_as_float(f2tf(sf[nt][1])));
            float2 p1 = make_float2(__uint_as_float(f2tf(sf[nt][2])),
                                    __uint_as_float(f2tf(sf[nt][3])));
            *reinterpret_cast<float2*>(&Ps[(row0 + qr    ) * 68 + nt * 8 + 2 * qc]) = p0;
            *reinterpret_cast<float2*>(&Ps[(row0 + qr + 8) * 68 + nt * 8 + 2 * qc]) = p1;
        }
        __syncwarp();

        // O += P V
#pragma unroll
        for (int ks = 0; ks < 8; ks++) {
            const int kk = ks * 8;
            const uint32_t pa0 = __float_as_uint(Ps[(row0 + qr    ) * 68 + kk + qc    ]);
            const uint32_t pa1 = __float_as_uint(Ps[(row0 + qr + 8) * 68 + kk + qc    ]);
            const uint32_t pa2 = __float_as_uint(Ps[(row0 + qr    ) * 68 + kk + qc + 4]);
            const uint32_t pa3 = __float_as_uint(Ps[(row0 + qr + 8) * 68 + kk + qc + 4]);
#pragma unroll
            for (int nt = 0; nt < 8; nt++) {
                const uint32_t b0 = __float_as_uint(Vs[(kk + qc    ) * 72 + nt * 8 + qr]);
                const uint32_t b1 = __float_as_uint(Vs[(kk + qc + 4) * 72 + nt * 8 + qr]);
                mma_tf32(oacc[nt], pa0, pa1, pa2, pa3, b0, b1);
            }
        }
    }

    // epilogue
    const float inv0 = 1.f / l0;
    const float inv1 = 1.f / l1;
#pragma unroll
    for (int nt = 0; nt < 8; nt++) {
        float2 w0 = make_float2(oacc[nt][0] * inv0, oacc[nt][1] * inv0);
        float2 w1 = make_float2(oacc[nt][2] * inv1, oacc[nt][3] * inv1);
        *reinterpret_cast<float2*>(&O[(size_t)(q0 + row0 + qr    ) * D + h * HD + nt * 8 + 2 * qc]) = w0;
        *reinterpret_cast<float2*>(&O[(size_t)(q0 + row0 + qr + 8) * D + h * HD + nt * 8 + 2 * qc]) = w1;
    }
}

// ---------------------------------------------------------------------------
extern "C" void kernel_launch(void* const* d_in, const int* in_sizes, int n_in,
                              void* d_out, int out_size)
{
    const float* x_in = (const float*)d_in[0];
    const float* ts   = (const float*)d_in[1];
    const float* ctx  = (const float*)d_in[2];
    const float* rope = (const float*)d_in[3];
    const float* adaW = (const float*)d_in[4];
    const float* adab = (const float*)d_in[5];
    const float* sqW  = (const float*)d_in[6];
    const float* skW  = (const float*)d_in[7];
    const float* svW  = (const float*)d_in[8];
    const float* soW  = (const float*)d_in[9];
    const float* sob  = (const float*)d_in[10];
    const float* cqW  = (const float*)d_in[11];
    const float* ckW  = (const float*)d_in[12];
    const float* cvW  = (const float*)d_in[13];
    const float* coW  = (const float*)d_in[14];
    const float* cob  = (const float*)d_in[15];
    const float* f1W  = (const float*)d_in[16];
    const float* f1b  = (const float*)d_in[17];
    const float* f2W  = (const float*)d_in[18];
    const float* f2b  = (const float*)d_in[19];

    float* x = (float*)d_out;

    float *hx, *q, *k, *v, *o, *ckb, *cvb, *hbuf, *kt, *mods;
    cudaGetSymbolAddress((void**)&hx,   g_hx);
    cudaGetSymbolAddress((void**)&q,    g_q);
    cudaGetSymbolAddress((void**)&k,    g_k);
    cudaGetSymbolAddress((void**)&v,    g_v);
    cudaGetSymbolAddress((void**)&o,    g_o);
    cudaGetSymbolAddress((void**)&ckb,  g_ck);
    cudaGetSymbolAddress((void**)&cvb,  g_cv);
    cudaGetSymbolAddress((void**)&hbuf, g_h);
    cudaGetSymbolAddress((void**)&kt,   g_kt);
    cudaGetSymbolAddress((void**)&mods, g_mods);

    const int ATTN_SMEM = (2 * 64 * 72 + 64 * 68) * sizeof(float);  // 54272
    cudaFuncSetAttribute(attn_mma, cudaFuncAttributeMaxDynamicSharedMemorySize, ATTN_SMEM);

    cudaMemcpyAsync(x, x_in, (size_t)L * D * sizeof(float), cudaMemcpyDeviceToDevice);

    const float scale = 0.125f; // 64^-0.5
    const dim3 gD  (D   / 128, L    / 128);
    const dim3 gDFF(DFF / 128, L    / 128);
    const dim3 gS  (D   / 128, SCTX / 128);
    const dim3 gAtt(L / 64, H);
    const dim3 gTrS(L / 32,    HD / 32, H);
    const dim3 gTrC(SCTX / 32, HD / 32, H);
    const dim3 bTr(32, 8);

    for (int i = 0; i < NB; i++) {
        const float* adaW_i = adaW + (size_t)i * 6 * D * D;
        const float* adab_i = adab + (size_t)i * 6 * D;
        const float* sqW_i  = sqW  + (size_t)i * D * D;
        const float* skW_i  = skW  + (size_t)i * D * D;
        const float* svW_i  = svW  + (size_t)i * D * D;
        const float* soW_i  = soW  + (size_t)i * D * D;
        const float* sob_i  = sob  + (size_t)i * D;
        const float* cqW_i  = cqW  + (size_t)i * D * D;
        const float* ckW_i  = ckW  + (size_t)i * D * D;
        const float* cvW_i  = cvW  + (size_t)i * D * D;
        const float* coW_i  = coW  + (size_t)i * D * D;
        const float* cob_i  = cob  + (size_t)i * D;
        const float* f1W_i  = f1W  + (size_t)i * DFF * D;
        const float* f1b_i  = f1b  + (size_t)i * DFF;
        const float* f2W_i  = f2W  + (size_t)i * D * DFF;
        const float* f2b_i  = f2b  + (size_t)i * D;

        // adaLN modulations
        gemv_ada<<<6 * D / 8, 256>>>(ts, adaW_i, adab_i, mods);

        // --- self attention ---
        ln_mod_kernel<<<L, 256>>>(x, mods, 0, D, hx);
        gemm_tf32<<<gD, 256>>>(hx, sqW_i, nullptr, nullptr, q, L, D, D, EP_STORE);
        gemm_tf32<<<gD, 256>>>(hx, skW_i, nullptr, nullptr, k, L, D, D, EP_STORE);
        gemm_tf32<<<gD, 256>>>(hx, svW_i, nullptr, nullptr, v, L, D, D, EP_STORE);
        rope_kernel<<<(L * H * 32) / 256, 256>>>(q, k, rope);
        transpose_k<<<gTrS, bTr>>>(k, kt, L);
        attn_mma<<<gAtt, 128, ATTN_SMEM>>>(q, kt, v, o, L, scale);
        gemm_tf32<<<gD, 256>>>(o, soW_i, sob_i, mods + 2 * D, x, L, D, D, EP_RESID_GATE);

        // --- cross attention ---
        ln_mod_kernel<<<L, 256>>>(x, nullptr, 0, 0, hx);
        gemm_tf32<<<gD, 256>>>(hx,  cqW_i, nullptr, nullptr, q,   L,    D, D, EP_STORE);
        gemm_tf32<<<gS, 256>>>(ctx, ckW_i, nullptr, nullptr, ckb, SCTX, D, D, EP_STORE);
        gemm_tf32<<<gS, 256>>>(ctx, cvW_i, nullptr, nullptr, cvb, SCTX, D, D, EP_STORE);
        transpose_k<<<gTrC, bTr>>>(ckb, kt, SCTX);
        attn_mma<<<gAtt, 128, ATTN_SMEM>>>(q, kt, cvb, o, SCTX, scale);
        gemm_tf32<<<gD, 256>>>(o, coW_i, cob_i, nullptr, x, L, D, D, EP_RESID);

        // --- MLP ---
        ln_mod_kernel<<<L, 256>>>(x, mods, 3 * D, 4 * D, hx);
        gemm_tf32<<<gDFF, 256>>>(hx,   f1W_i, f1b_i, nullptr,      hbuf, L, DFF, D,   EP_GELU);
        gemm_tf32<<<gD,   256>>>(hbuf, f2W_i, f2b_i, mods + 5 * D, x,    L, D,   DFF, EP_RESID_GATE);
    }
}

// round 4
// speedup vs baseline: 3.3704x; 1.4739x over previous
#include <cuda_runtime.h>
#include <math.h>
#include <stdint.h>

// Problem constants
constexpr int L    = 3072;
constexpr int D    = 1024;
constexpr int H    = 16;
constexpr int HD   = 64;
constexpr int SCTX = 512;
constexpr int DFF  = 4096;
constexpr int NB   = 2;

// ---------------- scratch (static device arrays; no cudaMalloc allowed) ----
__device__ float g_hx[(size_t)L * D];
__device__ float g_q [(size_t)L * D];
__device__ float g_k [(size_t)L * D];
__device__ float g_v [(size_t)L * D];
__device__ float g_o [(size_t)L * D];
__device__ float g_ck[(size_t)SCTX * D];
__device__ float g_cv[(size_t)SCTX * D];
__device__ float g_h [(size_t)L * DFF];
__device__ float g_kt[(size_t)H * HD * L];   // K^T [h][d][l]
__device__ float g_mods[6 * D];

enum { EP_STORE = 0, EP_GELU = 1, EP_RESID = 2, EP_RESID_GATE = 3 };

__device__ __forceinline__ uint32_t f2tf(float x) {
    uint32_t r;
    asm("cvt.rna.tf32.f32 %0, %1;" : "=r"(r) : "f"(x));
    return r;
}

__device__ __forceinline__ void mma_tf32(float c[4], uint32_t a0, uint32_t a1,
                                         uint32_t a2, uint32_t a3,
                                         uint32_t b0, uint32_t b1) {
    asm volatile(
        "mma.sync.aligned.m16n8k8.row.col.f32.tf32.tf32.f32 "
        "{%0,%1,%2,%3}, {%4,%5,%6,%7}, {%8,%9}, {%0,%1,%2,%3};"
        : "+f"(c[0]), "+f"(c[1]), "+f"(c[2]), "+f"(c[3])
        : "r"(a0), "r"(a1), "r"(a2), "r"(a3), "r"(b0), "r"(b1));
}

__device__ __forceinline__ void cp_async16(uint32_t saddr, const void* gaddr) {
    asm volatile("cp.async.cg.shared.global [%0], [%1], 16;\n"
                 :: "r"(saddr), "l"(gaddr));
}
__device__ __forceinline__ void cp_commit() {
    asm volatile("cp.async.commit_group;\n");
}
template <int N>
__device__ __forceinline__ void cp_wait() {
    asm volatile("cp.async.wait_group %0;\n" :: "n"(N));
}

// ---------------------------------------------------------------------------
// TF32 tensor-core GEMM, 4-stage cp.async pipeline.
// C[M,N] (+epilogue) = A[M,K] (row-major) x W[N,K]^T
// BM=BN=128, BK=16, 256 threads = 8 warps (2 M x 4 N), warp tile 64x32.
// Smem tiles m-major [128][20]: stride 20 == 4 (mod 32) -> fragment LDS
// bank map 4*qr+qc is bijective (conflict-free). tf32 cvt post-LDS (RNA).
// blockIdx.z selects among up to 3 weight/output pairs (fused QKV etc.)
// ---------------------------------------------------------------------------
constexpr int GSTAGES = 4;
constexpr int GBK     = 16;
constexpr int GSROW   = 20;                         // 16 + 4 pad
constexpr int GTILE_F = 128 * GSROW;                // floats per tile
constexpr int GEMM_SMEM = 2 * GSTAGES * GTILE_F * 4; // 81920 bytes

__global__ void __launch_bounds__(256, 2) gemm_tf32(
    const float* __restrict__ A,
    const float* __restrict__ W0, const float* __restrict__ W1,
    const float* __restrict__ W2,
    const float* __restrict__ bias, const float* __restrict__ gate,
    float* __restrict__ C0, float* __restrict__ C1, float* __restrict__ C2,
    int M, int N, int K, int mode)
{
    extern __shared__ float smem[];
    float* As = smem;                       // [GSTAGES][128][GSROW]
    float* Bs = smem + GSTAGES * GTILE_F;

    const float* W = (blockIdx.z == 0) ? W0 : (blockIdx.z == 1) ? W1 : W2;
    float*       C = (blockIdx.z == 0) ? C0 : (blockIdx.z == 1) ? C1 : C2;

    const int tid  = threadIdx.x;
    const int m0   = blockIdx.y * 128;
    const int n0   = blockIdx.x * 128;
    const int lane = tid & 31;
    const int warp = tid >> 5;
    const int mwb  = (warp & 1) * 64;
    const int nwb  = (warp >> 1) * 32;
    const int qr   = lane >> 2;
    const int qc   = lane & 3;

    const uint32_t sA0 = (uint32_t)__cvta_generic_to_shared(As);
    const uint32_t sB0 = (uint32_t)__cvta_generic_to_shared(Bs);

    // loader: 512 16B-chunks per tile, 2 per thread. chunk -> (row, k0)
    const int lrow0 = tid >> 2;            // chunk i=0 row (0..63)
    const int lk    = (tid & 3) * 4;

    float acc[4][4][4];
#pragma unroll
    for (int i = 0; i < 4; i++)
#pragma unroll
        for (int j = 0; j < 4; j++)
#pragma unroll
            for (int e = 0; e < 4; e++) acc[i][j][e] = 0.f;

    const int nT = K >> 4;

    auto ld_stage = [&](int slot, int t) {
        const int kb = t * GBK;
#pragma unroll
        for (int i = 0; i < 2; i++) {
            const int row = lrow0 + i * 64;
            const uint32_t off = (uint32_t)((slot * 128 + row) * GSROW + lk) * 4u;
            cp_async16(sA0 + off, &A[(size_t)(m0 + row) * K + kb + lk]);
            cp_async16(sB0 + off, &W[(size_t)(n0 + row) * K + kb + lk]);
        }
    };

    // prologue: 3 stages in flight
#pragma unroll
    for (int s = 0; s < GSTAGES - 1; s++) {
        if (s < nT) ld_stage(s, s);
        cp_commit();
    }

    for (int t = 0; t < nT; t++) {
        cp_wait<GSTAGES - 2>();
        __syncthreads();

        // issue next stage (into the slot compute just vacated last iter)
        if (t + GSTAGES - 1 < nT) ld_stage((t + GSTAGES - 1) & (GSTAGES - 1), t + GSTAGES - 1);
        cp_commit();

        const int slot = t & (GSTAGES - 1);
        const float* At = As + slot * GTILE_F + mwb * GSROW;
        const float* Bt = Bs + slot * GTILE_F + nwb * GSROW;

#pragma unroll
        for (int ks = 0; ks < 2; ks++) {
            const int kk = ks * 8;
            uint32_t afr[4][4], bfr[4][2];
#pragma unroll
            for (int mt = 0; mt < 4; mt++) {
                const int mb = mt * 16;
                afr[mt][0] = f2tf(At[(mb + qr    ) * GSROW + kk + qc    ]);
                afr[mt][1] = f2tf(At[(mb + qr + 8) * GSROW + kk + qc    ]);
                afr[mt][2] = f2tf(At[(mb + qr    ) * GSROW + kk + qc + 4]);
                afr[mt][3] = f2tf(At[(mb + qr + 8) * GSROW + kk + qc + 4]);
            }
#pragma unroll
            for (int nt = 0; nt < 4; nt++) {
                const int nb = nt * 8;
                bfr[nt][0] = f2tf(Bt[(nb + qr) * GSROW + kk + qc    ]);
                bfr[nt][1] = f2tf(Bt[(nb + qr) * GSROW + kk + qc + 4]);
            }
#pragma unroll
            for (int mt = 0; mt < 4; mt++)
#pragma unroll
                for (int nt = 0; nt < 4; nt++)
                    mma_tf32(acc[mt][nt], afr[mt][0], afr[mt][1], afr[mt][2],
                             afr[mt][3], bfr[nt][0], bfr[nt][1]);
        }
    }

    // epilogue
#pragma unroll
    for (int mt = 0; mt < 4; mt++) {
#pragma unroll
        for (int nt = 0; nt < 4; nt++) {
#pragma unroll
            for (int half = 0; half < 2; half++) {
                const int r = m0 + mwb + mt * 16 + qr + half * 8;
#pragma unroll
                for (int e = 0; e < 2; e++) {
                    const int c = n0 + nwb + nt * 8 + 2 * qc + e;
                    float val = acc[mt][nt][half * 2 + e];
                    val += bias ? bias[c] : 0.f;
                    float* Cp = C + (size_t)r * N + c;
                    if (mode == EP_STORE) {
                        *Cp = val;
                    } else if (mode == EP_GELU) {
                        *Cp = 0.5f * val * (1.f + erff(val * 0.70710678118654752f));
                    } else if (mode == EP_RESID) {
                        *Cp += val;
                    } else {
                        *Cp += gate[c] * val;
                    }
                }
            }
        }
    }
}

// ---------------------------------------------------------------------------
// adaLN modulation GEMV
// ---------------------------------------------------------------------------
__global__ void __launch_bounds__(256) gemv_ada(
    const float* __restrict__ t, const float* __restrict__ Wt,
    const float* __restrict__ b, float* __restrict__ out)
{
    const int o    = blockIdx.x * 8 + (threadIdx.x >> 5);
    const int lane = threadIdx.x & 31;
    const float* wr = Wt + (size_t)o * D;
    float s = 0.f;
    for (int d = lane; d < D; d += 32) s = fmaf(t[d], wr[d], s);
#pragma unroll
    for (int off = 16; off; off >>= 1) s += __shfl_xor_sync(0xffffffffu, s, off);
    if (lane == 0) out[o] = s + b[o];
}

// ---------------------------------------------------------------------------
// LayerNorm (+ optional adaLN shift/scale)
// ---------------------------------------------------------------------------
__global__ void __launch_bounds__(256) ln_mod_kernel(
    const float* __restrict__ x, const float* __restrict__ mods,
    int sh_off, int sc_off, float* __restrict__ y)
{
    __shared__ float red[8];
    __shared__ float bval;
    const int row = blockIdx.x;
    const int t = threadIdx.x;
    const float* xr = x + (size_t)row * D;

    float v[4];
    float s = 0.f;
#pragma unroll
    for (int j = 0; j < 4; j++) { v[j] = xr[t + j * 256]; s += v[j]; }
#pragma unroll
    for (int off = 16; off; off >>= 1) s += __shfl_xor_sync(0xffffffffu, s, off);
    if ((t & 31) == 0) red[t >> 5] = s;
    __syncthreads();
    if (t == 0) {
        float tot = 0.f;
        for (int j = 0; j < 8; j++) tot += red[j];
        bval = tot * (1.f / D);
    }
    __syncthreads();
    const float mean = bval;

    float vs = 0.f;
#pragma unroll
    for (int j = 0; j < 4; j++) { float d = v[j] - mean; vs = fmaf(d, d, vs); }
#pragma unroll
    for (int off = 16; off; off >>= 1) vs += __shfl_xor_sync(0xffffffffu, vs, off);
    if ((t & 31) == 0) red[t >> 5] = vs;
    __syncthreads();
    if (t == 0) {
        float tot = 0.f;
        for (int j = 0; j < 8; j++) tot += red[j];
        bval = rsqrtf(tot * (1.f / D) + 1e-6f);
    }
    __syncthreads();
    const float rstd = bval;

    float* yr = y + (size_t)row * D;
#pragma unroll
    for (int j = 0; j < 4; j++) {
        const int d = t + j * 256;
        const float sc = mods ? mods[sc_off + d] : 0.f;
        const float sh = mods ? mods[sh_off + d] : 0.f;
        yr[d] = (v[j] - mean) * rstd * (1.f + sc) + sh;
    }
}

// ---------------------------------------------------------------------------
// RoPE (in place, on q and k)
// ---------------------------------------------------------------------------
__global__ void __launch_bounds__(256) rope_kernel(
    float* __restrict__ q, float* __restrict__ k, const float* __restrict__ rope)
{
    const int idx = blockIdx.x * 256 + threadIdx.x;
    if (idx >= L * H * 32) return;
    const int j = idx & 31;
    const int h = (idx >> 5) & 15;
    const int l = idx >> 9;
    const float a1 = rope[l * HD + j];
    const float a2 = rope[l * HD + j + 32];
    const float c1 = cosf(a1), s1 = sinf(a1);
    const float c2 = cosf(a2), s2 = sinf(a2);
    const size_t base = (size_t)l * D + h * HD;

    float q1 = q[base + j], q2 = q[base + j + 32];
    q[base + j]      = q1 * c1 - q2 * s1;
    q[base + j + 32] = q2 * c2 + q1 * s2;

    float k1 = k[base + j], k2 = k[base + j + 32];
    k[base + j]      = k1 * c1 - k2 * s1;
    k[base + j + 32] = k2 * c2 + k1 * s2;
}

// ---------------------------------------------------------------------------
// K transpose: Kin [Lk x D (head h at cols h*64..)] -> KT [h][d][l], tf32.
// ---------------------------------------------------------------------------
__global__ void __launch_bounds__(256) transpose_k(
    const float* __restrict__ Kin, float* __restrict__ KT, int Lk)
{
    __shared__ float t[32][33];
    const int h  = blockIdx.z;
    const int d0 = blockIdx.y * 32;
    const int l0 = blockIdx.x * 32;
    const int tx = threadIdx.x, ty = threadIdx.y;
#pragma unroll
    for (int j = 0; j < 4; j++)
        t[ty + j * 8][tx] = Kin[(size_t)(l0 + ty + j * 8) * D + h * HD + d0 + tx];
    __syncthreads();
#pragma unroll
    for (int j = 0; j < 4; j++)
        KT[(size_t)h * HD * Lk + (size_t)(d0 + ty + j * 8) * Lk + l0 + tx] =
            __uint_as_float(f2tf(t[tx][ty + j * 8]));
}

// ---------------------------------------------------------------------------
// Tensor-core flash attention (tf32) — unchanged from R3.
// ---------------------------------------------------------------------------
__global__ void __launch_bounds__(128) attn_mma(
    const float* __restrict__ Q, const float* __restrict__ KT,
    const float* __restrict__ Vp, float* __restrict__ O,
    int Lk, float scale)
{
    extern __shared__ float sm[];
    float* Ks = sm;                  // [64][72]
    float* Vs = sm + 64 * 72;        // [64][72]
    float* Ps = sm + 2 * 64 * 72;    // [64][68]

    const int tid  = threadIdx.x;
    const int warp = tid >> 5;
    const int lane = tid & 31;
    const int qr = lane >> 2, qc = lane & 3;
    const int h  = blockIdx.y;
    const int q0 = blockIdx.x * 64;
    const int row0 = warp * 16;

    for (int i = tid; i < 64 * 16; i += 128) {
        const int r = i >> 4, c4 = (i & 15) * 4;
        float4 qv = *reinterpret_cast<const float4*>(&Q[(size_t)(q0 + r) * D + h * HD + c4]);
        float* dst = &Ps[r * 68 + c4];
        dst[0] = qv.x * scale; dst[1] = qv.y * scale;
        dst[2] = qv.z * scale; dst[3] = qv.w * scale;
    }
    __syncthreads();

    uint32_t qf[8][4];
#pragma unroll
    for (int ks = 0; ks < 8; ks++) {
        const int kk = ks * 8;
        qf[ks][0] = f2tf(Ps[(row0 + qr    ) * 68 + kk + qc    ]);
        qf[ks][1] = f2tf(Ps[(row0 + qr + 8) * 68 + kk + qc    ]);
        qf[ks][2] = f2tf(Ps[(row0 + qr    ) * 68 + kk + qc + 4]);
        qf[ks][3] = f2tf(Ps[(row0 + qr + 8) * 68 + kk + qc + 4]);
    }

    float m0 = -1e30f, m1 = -1e30f, l0 = 0.f, l1 = 0.f;
    float oacc[8][4];
#pragma unroll
    for (int nt = 0; nt < 8; nt++)
#pragma unroll
        for (int e = 0; e < 4; e++) oacc[nt][e] = 0.f;

    const float* KTh = KT + (size_t)h * HD * Lk;

    for (int kt = 0; kt < Lk; kt += 64) {
        __syncthreads();
        for (int i = tid; i < 64 * 16; i += 128) {
            const int r = i >> 4, c4 = (i & 15) * 4;
            float4 kv = *reinterpret_cast<const float4*>(&KTh[(size_t)r * Lk + kt + c4]);
            *reinterpret_cast<float4*>(&Ks[r * 72 + c4]) = kv;
            float4 vv = *reinterpret_cast<const float4*>(&Vp[(size_t)(kt + r) * D + h * HD + c4]);
            float4 vr;
            vr.x = __uint_as_float(f2tf(vv.x));
            vr.y = __uint_as_float(f2tf(vv.y));
            vr.z = __uint_as_float(f2tf(vv.z));
            vr.w = __uint_as_float(f2tf(vv.w));
            *reinterpret_cast<float4*>(&Vs[r * 72 + c4]) = vr;
        }
        __syncthreads();

        float sf[8][4];
#pragma unroll
        for (int nt = 0; nt < 8; nt++)
#pragma unroll
            for (int e = 0; e < 4; e++) sf[nt][e] = 0.f;
#pragma unroll
        for (int ks = 0; ks < 8; ks++) {
            const int kk = ks * 8;
#pragma unroll
            for (int nt = 0; nt < 8; nt++) {
                const uint32_t b0 = __float_as_uint(Ks[(kk + qc    ) * 72 + nt * 8 + qr]);
                const uint32_t b1 = __float_as_uint(Ks[(kk + qc + 4) * 72 + nt * 8 + qr]);
                mma_tf32(sf[nt], qf[ks][0], qf[ks][1], qf[ks][2], qf[ks][3], b0, b1);
            }
        }

        float rmax0 = -1e30f, rmax1 = -1e30f;
#pragma unroll
        for (int nt = 0; nt < 8; nt++) {
            rmax0 = fmaxf(rmax0, fmaxf(sf[nt][0], sf[nt][1]));
            rmax1 = fmaxf(rmax1, fmaxf(sf[nt][2], sf[nt][3]));
        }
        rmax0 = fmaxf(rmax0, __shfl_xor_sync(0xffffffffu, rmax0, 1));
        rmax0 = fmaxf(rmax0, __shfl_xor_sync(0xffffffffu, rmax0, 2));
        rmax1 = fmaxf(rmax1, __shfl_xor_sync(0xffffffffu, rmax1, 1));
        rmax1 = fmaxf(rmax1, __shfl_xor_sync(0xffffffffu, rmax1, 2));

        const float mn0 = fmaxf(m0, rmax0);
        const float mn1 = fmaxf(m1, rmax1);
        const float a0 = __expf(m0 - mn0);
        const float a1 = __expf(m1 - mn1);
        float rs0 = 0.f, rs1 = 0.f;
#pragma unroll
        for (int nt = 0; nt < 8; nt++) {
            sf[nt][0] = __expf(sf[nt][0] - mn0);
            sf[nt][1] = __expf(sf[nt][1] - mn0);
            sf[nt][2] = __expf(sf[nt][2] - mn1);
            sf[nt][3] = __expf(sf[nt][3] - mn1);
            rs0 += sf[nt][0] + sf[nt][1];
            rs1 += sf[nt][2] + sf[nt][3];
        }
        rs0 += __shfl_xor_sync(0xffffffffu, rs0, 1);
        rs0 += __shfl_xor_sync(0xffffffffu, rs0, 2);
        rs1 += __shfl_xor_sync(0xffffffffu, rs1, 1);
        rs1 += __shfl_xor_sync(0xffffffffu, rs1, 2);
        l0 = l0 * a0 + rs0;
        l1 = l1 * a1 + rs1;
        m0 = mn0; m1 = mn1;
#pragma unroll
        for (int nt = 0; nt < 8; nt++) {
            oacc[nt][0] *= a0; oacc[nt][1] *= a0;
            oacc[nt][2] *= a1; oacc[nt][3] *= a1;
        }

        __syncwarp();
#pragma unroll
        for (int nt = 0; nt < 8; nt++) {
            float2 p0 = make_float2(__uint_as_float(f2tf(sf[nt][0])),
                                    __uint_as_float(f2tf(sf[nt][1])));
            float2 p1 = make_float2(__uint_as_float(f2tf(sf[nt][2])),
                                    __uint_as_float(f2tf(sf[nt][3])));
            *reinterpret_cast<float2*>(&Ps[(row0 + qr    ) * 68 + nt * 8 + 2 * qc]) = p0;
            *reinterpret_cast<float2*>(&Ps[(row0 + qr + 8) * 68 + nt * 8 + 2 * qc]) = p1;
        }
        __syncwarp();

#pragma unroll
        for (int ks = 0; ks < 8; ks++) {
            const int kk = ks * 8;
            const uint32_t pa0 = __float_as_uint(Ps[(row0 + qr    ) * 68 + kk + qc    ]);
            const uint32_t pa1 = __float_as_uint(Ps[(row0 + qr + 8) * 68 + kk + qc    ]);
            const uint32_t pa2 = __float_as_uint(Ps[(row0 + qr    ) * 68 + kk + qc + 4]);
            const uint32_t pa3 = __float_as_uint(Ps[(row0 + qr + 8) * 68 + kk + qc + 4]);
#pragma unroll
            for (int nt = 0; nt < 8; nt++) {
                const uint32_t b0 = __float_as_uint(Vs[(kk + qc    ) * 72 + nt * 8 + qr]);
                const uint32_t b1 = __float_as_uint(Vs[(kk + qc + 4) * 72 + nt * 8 + qr]);
                mma_tf32(oacc[nt], pa0, pa1, pa2, pa3, b0, b1);
            }
        }
    }

    const float inv0 = 1.f / l0;
    const float inv1 = 1.f / l1;
#pragma unroll
    for (int nt = 0; nt < 8; nt++) {
        float2 w0 = make_float2(oacc[nt][0] * inv0, oacc[nt][1] * inv0);
        float2 w1 = make_float2(oacc[nt][2] * inv1, oacc[nt][3] * inv1);
        *reinterpret_cast<float2*>(&O[(size_t)(q0 + row0 + qr    ) * D + h * HD + nt * 8 + 2 * qc]) = w0;
        *reinterpret_cast<float2*>(&O[(size_t)(q0 + row0 + qr + 8) * D + h * HD + nt * 8 + 2 * qc]) = w1;
    }
}

// ---------------------------------------------------------------------------
extern "C" void kernel_launch(void* const* d_in, const int* in_sizes, int n_in,
                              void* d_out, int out_size)
{
    const float* x_in = (const float*)d_in[0];
    const float* ts   = (const float*)d_in[1];
    const float* ctx  = (const float*)d_in[2];
    const float* rope = (const float*)d_in[3];
    const float* adaW = (const float*)d_in[4];
    const float* adab = (const float*)d_in[5];
    const float* sqW  = (const float*)d_in[6];
    const float* skW  = (const float*)d_in[7];
    const float* svW  = (const float*)d_in[8];
    const float* soW  = (const float*)d_in[9];
    const float* sob  = (const float*)d_in[10];
    const float* cqW  = (const float*)d_in[11];
    const float* ckW  = (const float*)d_in[12];
    const float* cvW  = (const float*)d_in[13];
    const float* coW  = (const float*)d_in[14];
    const float* cob  = (const float*)d_in[15];
    const float* f1W  = (const float*)d_in[16];
    const float* f1b  = (const float*)d_in[17];
    const float* f2W  = (const float*)d_in[18];
    const float* f2b  = (const float*)d_in[19];

    float* x = (float*)d_out;

    float *hx, *q, *k, *v, *o, *ckb, *cvb, *hbuf, *kt, *mods;
    cudaGetSymbolAddress((void**)&hx,   g_hx);
    cudaGetSymbolAddress((void**)&q,    g_q);
    cudaGetSymbolAddress((void**)&k,    g_k);
    cudaGetSymbolAddress((void**)&v,    g_v);
    cudaGetSymbolAddress((void**)&o,    g_o);
    cudaGetSymbolAddress((void**)&ckb,  g_ck);
    cudaGetSymbolAddress((void**)&cvb,  g_cv);
    cudaGetSymbolAddress((void**)&hbuf, g_h);
    cudaGetSymbolAddress((void**)&kt,   g_kt);
    cudaGetSymbolAddress((void**)&mods, g_mods);

    const int ATTN_SMEM = (2 * 64 * 72 + 64 * 68) * sizeof(float);  // 54272
    cudaFuncSetAttribute(attn_mma, cudaFuncAttributeMaxDynamicSharedMemorySize, ATTN_SMEM);
    cudaFuncSetAttribute(gemm_tf32, cudaFuncAttributeMaxDynamicSharedMemorySize, GEMM_SMEM);

    cudaMemcpyAsync(x, x_in, (size_t)L * D * sizeof(float), cudaMemcpyDeviceToDevice);

    const float scale = 0.125f; // 64^-0.5
    const dim3 gQKV(D   / 128, L    / 128, 3);
    const dim3 gD  (D   / 128, L    / 128, 1);
    const dim3 gDFF(DFF / 128, L    / 128, 1);
    const dim3 gKV (D   / 128, SCTX / 128, 2);
    const dim3 gAtt(L / 64, H);
    const dim3 gTrS(L / 32,    HD / 32, H);
    const dim3 gTrC(SCTX / 32, HD / 32, H);
    const dim3 bTr(32, 8);

    for (int i = 0; i < NB; i++) {
        const float* adaW_i = adaW + (size_t)i * 6 * D * D;
        const float* adab_i = adab + (size_t)i * 6 * D;
        const float* sqW_i  = sqW  + (size_t)i * D * D;
        const float* skW_i  = skW  + (size_t)i * D * D;
        const float* svW_i  = svW  + (size_t)i * D * D;
        const float* soW_i  = soW  + (size_t)i * D * D;
        const float* sob_i  = sob  + (size_t)i * D;
        const float* cqW_i  = cqW  + (size_t)i * D * D;
        const float* ckW_i  = ckW  + (size_t)i * D * D;
        const float* cvW_i  = cvW  + (size_t)i * D * D;
        const float* coW_i  = coW  + (size_t)i * D * D;
        const float* cob_i  = cob  + (size_t)i * D;
        const float* f1W_i  = f1W  + (size_t)i * DFF * D;
        const float* f1b_i  = f1b  + (size_t)i * DFF;
        const float* f2W_i  = f2W  + (size_t)i * D * DFF;
        const float* f2b_i  = f2b  + (size_t)i * D;

        gemv_ada<<<6 * D / 8, 256>>>(ts, adaW_i, adab_i, mods);

        // --- self attention ---
        ln_mod_kernel<<<L, 256>>>(x, mods, 0, D, hx);
        gemm_tf32<<<gQKV, 256, GEMM_SMEM>>>(hx, sqW_i, skW_i, svW_i, nullptr, nullptr,
                                            q, k, v, L, D, D, EP_STORE);
        rope_kernel<<<(L * H * 32) / 256, 256>>>(q, k, rope);
        transpose_k<<<gTrS, bTr>>>(k, kt, L);
        attn_mma<<<gAtt, 128, ATTN_SMEM>>>(q, kt, v, o, L, scale);
        gemm_tf32<<<gD, 256, GEMM_SMEM>>>(o, soW_i, nullptr, nullptr, sob_i, mods + 2 * D,
                                          x, nullptr, nullptr, L, D, D, EP_RESID_GATE);

        // --- cross attention ---
        ln_mod_kernel<<<L, 256>>>(x, nullptr, 0, 0, hx);
        gemm_tf32<<<gD, 256, GEMM_SMEM>>>(hx, cqW_i, nullptr, nullptr, nullptr, nullptr,
                                          q, nullptr, nullptr, L, D, D, EP_STORE);
        gemm_tf32<<<gKV, 256, GEMM_SMEM>>>(ctx, ckW_i, cvW_i, nullptr, nullptr, nullptr,
                                           ckb, cvb, nullptr, SCTX, D, D, EP_STORE);
        transpose_k<<<gTrC, bTr>>>(ckb, kt, SCTX);
        attn_mma<<<gAtt, 128, ATTN_SMEM>>>(q, kt, cvb, o, SCTX, scale);
        gemm_tf32<<<gD, 256, GEMM_SMEM>>>(o, coW_i, nullptr, nullptr, cob_i, nullptr,
                                          x, nullptr, nullptr, L, D, D, EP_RESID);

        // --- MLP ---
        ln_mod_kernel<<<L, 256>>>(x, mods, 3 * D, 4 * D, hx);
        gemm_tf32<<<gDFF, 256, GEMM_SMEM>>>(hx, f1W_i, nullptr, nullptr, f1b_i, nullptr,
                                            hbuf, nullptr, nullptr, L, DFF, D, EP_GELU);
        gemm_tf32<<<gD, 256, GEMM_SMEM>>>(hbuf, f2W_i, nullptr, nullptr, f2b_i, mods + 5 * D,
                                          x, nullptr, nullptr, L, D, DFF, EP_RESID_GATE);
    }
}

// round 6
// speedup vs baseline: 3.6403x; 1.0801x over previous
#include <cuda_runtime.h>
#include <math.h>
#include <stdint.h>

// Problem constants
constexpr int L    = 3072;
constexpr int D    = 1024;
constexpr int H    = 16;
constexpr int HD   = 64;
constexpr int SCTX = 512;
constexpr int DFF  = 4096;
constexpr int NB   = 2;

// ---------------- scratch (static device arrays; no cudaMalloc allowed) ----
__device__ float g_hx[(size_t)L * D];
__device__ float g_q [(size_t)L * D];
__device__ float g_k [(size_t)L * D];
__device__ float g_v [(size_t)L * D];
__device__ float g_o [(size_t)L * D];
__device__ float g_ck[(size_t)SCTX * D];
__device__ float g_cv[(size_t)SCTX * D];
__device__ float g_h [(size_t)L * DFF];
__device__ float g_kt[(size_t)H * HD * L];   // K^T [h][d][l]
__device__ float g_mods[6 * D];

enum { EP_STORE = 0, EP_GELU = 1, EP_RESID = 2, EP_RESID_GATE = 3 };

__device__ __forceinline__ uint32_t f2tf(float x) {
    uint32_t r;
    asm("cvt.rna.tf32.f32 %0, %1;" : "=r"(r) : "f"(x));
    return r;
}

__device__ __forceinline__ void mma_tf32(float c[4], uint32_t a0, uint32_t a1,
                                         uint32_t a2, uint32_t a3,
                                         uint32_t b0, uint32_t b1) {
    asm volatile(
        "mma.sync.aligned.m16n8k8.row.col.f32.tf32.tf32.f32 "
        "{%0,%1,%2,%3}, {%4,%5,%6,%7}, {%8,%9}, {%0,%1,%2,%3};"
        : "+f"(c[0]), "+f"(c[1]), "+f"(c[2]), "+f"(c[3])
        : "r"(a0), "r"(a1), "r"(a2), "r"(a3), "r"(b0), "r"(b1));
}

__device__ __forceinline__ void cp_async16(uint32_t saddr, const void* gaddr) {
    asm volatile("cp.async.cg.shared.global [%0], [%1], 16;\n"
                 :: "r"(saddr), "l"(gaddr));
}
__device__ __forceinline__ void cp_commit() {
    asm volatile("cp.async.commit_group;\n");
}
template <int N>
__device__ __forceinline__ void cp_wait() {
    asm volatile("cp.async.wait_group %0;\n" :: "n"(N));
}

// ---------------------------------------------------------------------------
// TF32 tensor-core GEMM, 3-stage cp.async pipeline, BK=32.
// C[M,N] (+epilogue) = A[M,K] (row-major) x W[N,K]^T
// BM=BN=128, 256 threads = 8 warps (2 M x 4 N), warp tile 64x32.
// Smem m-major [128][36]: 36 == 4 (mod 32) -> fragment LDS bank map
// (4*qr+qc) bijective, conflict-free. tf32 cvt (RNA) post-LDS.
// blockIdx.z selects among up to 3 weight/output pairs (fused QKV etc.)
// ---------------------------------------------------------------------------
constexpr int GSTAGES = 3;
constexpr int GBK     = 32;
constexpr int GSROW   = 36;                          // 32 + 4 pad
constexpr int GTILE_F = 128 * GSROW;                 // floats per tile
constexpr int GEMM_SMEM = 2 * GSTAGES * GTILE_F * 4; // 110592 bytes

__global__ void __launch_bounds__(256, 2) gemm_tf32(
    const float* __restrict__ A,
    const float* __restrict__ W0, const float* __restrict__ W1,
    const float* __restrict__ W2,
    const float* __restrict__ bias, const float* __restrict__ gate,
    float* __restrict__ C0, float* __restrict__ C1, float* __restrict__ C2,
    int M, int N, int K, int mode)
{
    extern __shared__ float smem[];
    float* As = smem;                       // [GSTAGES][128][GSROW]
    float* Bs = smem + GSTAGES * GTILE_F;

    const float* W = (blockIdx.z == 0) ? W0 : (blockIdx.z == 1) ? W1 : W2;
    float*       C = (blockIdx.z == 0) ? C0 : (blockIdx.z == 1) ? C1 : C2;

    const int tid  = threadIdx.x;
    const int m0   = blockIdx.y * 128;
    const int n0   = blockIdx.x * 128;
    const int lane = tid & 31;
    const int warp = tid >> 5;
    const int mwb  = (warp & 1) * 64;
    const int nwb  = (warp >> 1) * 32;
    const int qr   = lane >> 2;
    const int qc   = lane & 3;

    const uint32_t sA0 = (uint32_t)__cvta_generic_to_shared(As);
    const uint32_t sB0 = (uint32_t)__cvta_generic_to_shared(Bs);

    // loader: 1024 16B-chunks per matrix per tile, 4 per thread.
    const int lrow0 = tid >> 3;            // 0..31
    const int lk    = (tid & 7) * 4;       // 0..28

    float acc[4][4][4];
#pragma unroll
    for (int i = 0; i < 4; i++)
#pragma unroll
        for (int j = 0; j < 4; j++)
#pragma unroll
            for (int e = 0; e < 4; e++) acc[i][j][e] = 0.f;

    const int nT = K / GBK;

    auto ld_stage = [&](int slot, int t) {
        const int kb = t * GBK;
#pragma unroll
        for (int i = 0; i < 4; i++) {
            const int row = lrow0 + i * 32;
            const uint32_t off = (uint32_t)((slot * 128 + row) * GSROW + lk) * 4u;
            cp_async16(sA0 + off, &A[(size_t)(m0 + row) * K + kb + lk]);
            cp_async16(sB0 + off, &W[(size_t)(n0 + row) * K + kb + lk]);
        }
    };

    // prologue: 2 stages in flight
#pragma unroll
    for (int s = 0; s < GSTAGES - 1; s++) {
        if (s < nT) ld_stage(s, s);
        cp_commit();
    }

    int slot = 0;
    for (int t = 0; t < nT; t++) {
        cp_wait<GSTAGES - 2>();
        __syncthreads();

        // issue stage t+2 into the slot compute vacated last iteration
        {
            int ns = slot + 2; if (ns >= GSTAGES) ns -= GSTAGES;
            if (t + GSTAGES - 1 < nT) ld_stage(ns, t + GSTAGES - 1);
            cp_commit();
        }

        const float* At = As + slot * GTILE_F + mwb * GSROW;
        const float* Bt = Bs + slot * GTILE_F + nwb * GSROW;

#pragma unroll
        for (int ks = 0; ks < 4; ks++) {
            const int kk = ks * 8;
            uint32_t afr[4][4], bfr[4][2];
#pragma unroll
            for (int mt = 0; mt < 4; mt++) {
                const int mb = mt * 16;
                afr[mt][0] = f2tf(At[(mb + qr    ) * GSROW + kk + qc    ]);
                afr[mt][1] = f2tf(At[(mb + qr + 8) * GSROW + kk + qc    ]);
                afr[mt][2] = f2tf(At[(mb + qr    ) * GSROW + kk + qc + 4]);
                afr[mt][3] = f2tf(At[(mb + qr + 8) * GSROW + kk + qc + 4]);
            }
#pragma unroll
            for (int nt = 0; nt < 4; nt++) {
                const int nb = nt * 8;
                bfr[nt][0] = f2tf(Bt[(nb + qr) * GSROW + kk + qc    ]);
                bfr[nt][1] = f2tf(Bt[(nb + qr) * GSROW + kk + qc + 4]);
            }
#pragma unroll
            for (int mt = 0; mt < 4; mt++)
#pragma unroll
                for (int nt = 0; nt < 4; nt++)
                    mma_tf32(acc[mt][nt], afr[mt][0], afr[mt][1], afr[mt][2],
                             afr[mt][3], bfr[nt][0], bfr[nt][1]);
        }

        if (++slot >= GSTAGES) slot = 0;
    }

    // epilogue
#pragma unroll
    for (int mt = 0; mt < 4; mt++) {
#pragma unroll
        for (int nt = 0; nt < 4; nt++) {
#pragma unroll
            for (int half = 0; half < 2; half++) {
                const int r = m0 + mwb + mt * 16 + qr + half * 8;
#pragma unroll
                for (int e = 0; e < 2; e++) {
                    const int c = n0 + nwb + nt * 8 + 2 * qc + e;
                    float val = acc[mt][nt][half * 2 + e];
                    val += bias ? bias[c] : 0.f;
                    float* Cp = C + (size_t)r * N + c;
                    if (mode == EP_STORE) {
                        *Cp = val;
                    } else if (mode == EP_GELU) {
                        *Cp = 0.5f * val * (1.f + erff(val * 0.70710678118654752f));
                    } else if (mode == EP_RESID) {
                        *Cp += val;
                    } else {
                        *Cp += gate[c] * val;
                    }
                }
            }
        }
    }
}

// ---------------------------------------------------------------------------
// adaLN modulation GEMV
// ---------------------------------------------------------------------------
__global__ void __launch_bounds__(256) gemv_ada(
    const float* __restrict__ t, const float* __restrict__ Wt,
    const float* __restrict__ b, float* __restrict__ out)
{
    const int o    = blockIdx.x * 8 + (threadIdx.x >> 5);
    const int lane = threadIdx.x & 31;
    const float* wr = Wt + (size_t)o * D;
    float s = 0.f;
    for (int d = lane; d < D; d += 32) s = fmaf(t[d], wr[d], s);
#pragma unroll
    for (int off = 16; off; off >>= 1) s += __shfl_xor_sync(0xffffffffu, s, off);
    if (lane == 0) out[o] = s + b[o];
}

// ---------------------------------------------------------------------------
// LayerNorm (+ optional adaLN shift/scale)
// ---------------------------------------------------------------------------
__global__ void __launch_bounds__(256) ln_mod_kernel(
    const float* __restrict__ x, const float* __restrict__ mods,
    int sh_off, int sc_off, float* __restrict__ y)
{
    __shared__ float red[8];
    __shared__ float bval;
    const int row = blockIdx.x;
    const int t = threadIdx.x;
    const float* xr = x + (size_t)row * D;

    float v[4];
    float s = 0.f;
#pragma unroll
    for (int j = 0; j < 4; j++) { v[j] = xr[t + j * 256]; s += v[j]; }
#pragma unroll
    for (int off = 16; off; off >>= 1) s += __shfl_xor_sync(0xffffffffu, s, off);
    if ((t & 31) == 0) red[t >> 5] = s;
    __syncthreads();
    if (t == 0) {
        float tot = 0.f;
        for (int j = 0; j < 8; j++) tot += red[j];
        bval = tot * (1.f / D);
    }
    __syncthreads();
    const float mean = bval;

    float vs = 0.f;
#pragma unroll
    for (int j = 0; j < 4; j++) { float d = v[j] - mean; vs = fmaf(d, d, vs); }
#pragma unroll
    for (int off = 16; off; off >>= 1) vs += __shfl_xor_sync(0xffffffffu, vs, off);
    if ((t & 31) == 0) red[t >> 5] = vs;
    __syncthreads();
    if (t == 0) {
        float tot = 0.f;
        for (int j = 0; j < 8; j++) tot += red[j];
        bval = rsqrtf(tot * (1.f / D) + 1e-6f);
    }
    __syncthreads();
    const float rstd = bval;

    float* yr = y + (size_t)row * D;
#pragma unroll
    for (int j = 0; j < 4; j++) {
        const int d = t + j * 256;
        const float sc = mods ? mods[sc_off + d] : 0.f;
        const float sh = mods ? mods[sh_off + d] : 0.f;
        yr[d] = (v[j] - mean) * rstd * (1.f + sc) + sh;
    }
}

// ---------------------------------------------------------------------------
// RoPE (in place, on q and k)
// ---------------------------------------------------------------------------
__global__ void __launch_bounds__(256) rope_kernel(
    float* __restrict__ q, float* __restrict__ k, const float* __restrict__ rope)
{
    const int idx = blockIdx.x * 256 + threadIdx.x;
    if (idx >= L * H * 32) return;
    const int j = idx & 31;
    const int h = (idx >> 5) & 15;
    const int l = idx >> 9;
    const float a1 = rope[l * HD + j];
    const float a2 = rope[l * HD + j + 32];
    const float c1 = cosf(a1), s1 = sinf(a1);
    const float c2 = cosf(a2), s2 = sinf(a2);
    const size_t base = (size_t)l * D + h * HD;

    float q1 = q[base + j], q2 = q[base + j + 32];
    q[base + j]      = q1 * c1 - q2 * s1;
    q[base + j + 32] = q2 * c2 + q1 * s2;

    float k1 = k[base + j], k2 = k[base + j + 32];
    k[base + j]      = k1 * c1 - k2 * s1;
    k[base + j + 32] = k2 * c2 + k1 * s2;
}

// ---------------------------------------------------------------------------
// K transpose: Kin [Lk x D (head h at cols h*64..)] -> KT [h][d][l], tf32.
// ---------------------------------------------------------------------------
__global__ void __launch_bounds__(256) transpose_k(
    const float* __restrict__ Kin, float* __restrict__ KT, int Lk)
{
    __shared__ float t[32][33];
    const int h  = blockIdx.z;
    const int d0 = blockIdx.y * 32;
    const int l0 = blockIdx.x * 32;
    const int tx = threadIdx.x, ty = threadIdx.y;
#pragma unroll
    for (int j = 0; j < 4; j++)
        t[ty + j * 8][tx] = Kin[(size_t)(l0 + ty + j * 8) * D + h * HD + d0 + tx];
    __syncthreads();
#pragma unroll
    for (int j = 0; j < 4; j++)
        KT[(size_t)h * HD * Lk + (size_t)(d0 + ty + j * 8) * Lk + l0 + tx] =
            __uint_as_float(f2tf(t[tx][ty + j * 8]));
}

// ---------------------------------------------------------------------------
// Tensor-core flash attention (tf32) with cp.async overlap.
// Block: 64 queries x 1 head, 4 warps (16 rows each). KV tiles of 64.
// K in 2-stage ring (K[i+1] loads during S(i)); V single-buffered, its load
// issued at iteration top and waited only after softmax (hidden behind S).
// Strides: Ks/Vs 72 (==8 mod 32, conflict-free B-frag), Ps 68 (==4 mod 32).
// ---------------------------------------------------------------------------
constexpr int ATTN_SMEM = (2 * 64 * 72 + 64 * 72 + 64 * 68) * 4;  // 72704 B

__global__ void __launch_bounds__(128) attn_mma(
    const float* __restrict__ Q, const float* __restrict__ KT,
    const float* __restrict__ Vp, float* __restrict__ O,
    int Lk, float scale)
{
    extern __shared__ float sm[];
    float* Ks = sm;                    // [2][64][72]
    float* Vs = sm + 2 * 64 * 72;      // [64][72]
    float* Ps = sm + 3 * 64 * 72;      // [64][68]

    const int tid  = threadIdx.x;
    const int warp = tid >> 5;
    const int lane = tid & 31;
    const int qr = lane >> 2, qc = lane & 3;
    const int h  = blockIdx.y;
    const int q0 = blockIdx.x * 64;
    const int row0 = warp * 16;

    const float* KTh = KT + (size_t)h * HD * Lk;
    const uint32_t sKs = (uint32_t)__cvta_generic_to_shared(Ks);
    const uint32_t sVs = (uint32_t)__cvta_generic_to_shared(Vs);

    // issue K[0] immediately
    for (int i = tid; i < 64 * 16; i += 128) {
        const int r = i >> 4, c4 = (i & 15) * 4;
        cp_async16(sKs + (uint32_t)(r * 72 + c4) * 4u, &KTh[(size_t)r * Lk + c4]);
    }
    cp_commit();

    // stage Q (scaled) into Ps
    for (int i = tid; i < 64 * 16; i += 128) {
        const int r = i >> 4, c4 = (i & 15) * 4;
        float4 qv = *reinterpret_cast<const float4*>(&Q[(size_t)(q0 + r) * D + h * HD + c4]);
        float* dst = &Ps[r * 68 + c4];
        dst[0] = qv.x * scale; dst[1] = qv.y * scale;
        dst[2] = qv.z * scale; dst[3] = qv.w * scale;
    }
    __syncthreads();

    uint32_t qf[8][4];
#pragma unroll
    for (int ks = 0; ks < 8; ks++) {
        const int kk = ks * 8;
        qf[ks][0] = f2tf(Ps[(row0 + qr    ) * 68 + kk + qc    ]);
        qf[ks][1] = f2tf(Ps[(row0 + qr + 8) * 68 + kk + qc    ]);
        qf[ks][2] = f2tf(Ps[(row0 + qr    ) * 68 + kk + qc + 4]);
        qf[ks][3] = f2tf(Ps[(row0 + qr + 8) * 68 + kk + qc + 4]);
    }

    float m0 = -1e30f, m1 = -1e30f, l0 = 0.f, l1 = 0.f;
    float oacc[8][4];
#pragma unroll
    for (int nt = 0; nt < 8; nt++)
#pragma unroll
        for (int e = 0; e < 4; e++) oacc[nt][e] = 0.f;

    const int nTiles = Lk / 64;
    for (int ti = 0; ti < nTiles; ti++) {
        const int kt = ti * 64;
        float* Kb = Ks + (ti & 1) * 64 * 72;

        cp_wait<0>();        // K[ti] resident (V[ti-1] done earlier)
        __syncthreads();     // all warps done with Vs / K[other buf]

        // issue V[ti] (group a), then K[ti+1] (group b)
        for (int i = tid; i < 64 * 16; i += 128) {
            const int r = i >> 4, c4 = (i & 15) * 4;
            cp_async16(sVs + (uint32_t)(r * 72 + c4) * 4u,
                       &Vp[(size_t)(kt + r) * D + h * HD + c4]);
        }
        cp_commit();
        if (ti + 1 < nTiles) {
            const uint32_t kb2 = sKs + (uint32_t)(((ti + 1) & 1) * 64 * 72) * 4u;
            for (int i = tid; i < 64 * 16; i += 128) {
                const int r = i >> 4, c4 = (i & 15) * 4;
                cp_async16(kb2 + (uint32_t)(r * 72 + c4) * 4u,
                           &KTh[(size_t)r * Lk + kt + 64 + c4]);
            }
        }
        cp_commit();

        // S = Q K^T (K pre-rounded tf32)
        float sf[8][4];
#pragma unroll
        for (int nt = 0; nt < 8; nt++)
#pragma unroll
            for (int e = 0; e < 4; e++) sf[nt][e] = 0.f;
#pragma unroll
        for (int ks = 0; ks < 8; ks++) {
            const int kk = ks * 8;
#pragma unroll
            for (int nt = 0; nt < 8; nt++) {
                const uint32_t b0 = __float_as_uint(Kb[(kk + qc    ) * 72 + nt * 8 + qr]);
                const uint32_t b1 = __float_as_uint(Kb[(kk + qc + 4) * 72 + nt * 8 + qr]);
                mma_tf32(sf[nt], qf[ks][0], qf[ks][1], qf[ks][2], qf[ks][3], b0, b1);
            }
        }

        // online softmax
        float rmax0 = -1e30f, rmax1 = -1e30f;
#pragma unroll
        for (int nt = 0; nt < 8; nt++) {
            rmax0 = fmaxf(rmax0, fmaxf(sf[nt][0], sf[nt][1]));
            rmax1 = fmaxf(rmax1, fmaxf(sf[nt][2], sf[nt][3]));
        }
        rmax0 = fmaxf(rmax0, __shfl_xor_sync(0xffffffffu, rmax0, 1));
        rmax0 = fmaxf(rmax0, __shfl_xor_sync(0xffffffffu, rmax0, 2));
        rmax1 = fmaxf(rmax1, __shfl_xor_sync(0xffffffffu, rmax1, 1));
        rmax1 = fmaxf(rmax1, __shfl_xor_sync(0xffffffffu, rmax1, 2));

        const float mn0 = fmaxf(m0, rmax0);
        const float mn1 = fmaxf(m1, rmax1);
        const float a0 = __expf(m0 - mn0);
        const float a1 = __expf(m1 - mn1);
        float rs0 = 0.f, rs1 = 0.f;
#pragma unroll
        for (int nt = 0; nt < 8; nt++) {
            sf[nt][0] = __expf(sf[nt][0] - mn0);
            sf[nt][1] = __expf(sf[nt][1] - mn0);
            sf[nt][2] = __expf(sf[nt][2] - mn1);
            sf[nt][3] = __expf(sf[nt][3] - mn1);
            rs0 += sf[nt][0] + sf[nt][1];
            rs1 += sf[nt][2] + sf[nt][3];
        }
        rs0 += __shfl_xor_sync(0xffffffffu, rs0, 1);
        rs0 += __shfl_xor_sync(0xffffffffu, rs0, 2);
        rs1 += __shfl_xor_sync(0xffffffffu, rs1, 1);
        rs1 += __shfl_xor_sync(0xffffffffu, rs1, 2);
        l0 = l0 * a0 + rs0;
        l1 = l1 * a1 + rs1;
        m0 = mn0; m1 = mn1;
#pragma unroll
        for (int nt = 0; nt < 8; nt++) {
            oacc[nt][0] *= a0; oacc[nt][1] *= a0;
            oacc[nt][2] *= a1; oacc[nt][3] *= a1;
        }

        // P -> warp-private Ps rows (tf32-rounded)
        __syncwarp();
#pragma unroll
        for (int nt = 0; nt < 8; nt++) {
            float2 p0 = make_float2(__uint_as_float(f2tf(sf[nt][0])),
                                    __uint_as_float(f2tf(sf[nt][1])));
            float2 p1 = make_float2(__uint_as_float(f2tf(sf[nt][2])),
                                    __uint_as_float(f2tf(sf[nt][3])));
            *reinterpret_cast<float2*>(&Ps[(row0 + qr    ) * 68 + nt * 8 + 2 * qc]) = p0;
            *reinterpret_cast<float2*>(&Ps[(row0 + qr + 8) * 68 + nt * 8 + 2 * qc]) = p1;
        }
        __syncwarp();

        // V[ti] landed? (K[ti+1] may still be in flight)
        cp_wait<1>();
        __syncthreads();

        // O += P V  (V rounded at fragment load)
#pragma unroll
        for (int ks = 0; ks < 8; ks++) {
            const int kk = ks * 8;
            const uint32_t pa0 = __float_as_uint(Ps[(row0 + qr    ) * 68 + kk + qc    ]);
            const uint32_t pa1 = __float_as_uint(Ps[(row0 + qr + 8) * 68 + kk + qc    ]);
            const uint32_t pa2 = __float_as_uint(Ps[(row0 + qr    ) * 68 + kk + qc + 4]);
            const uint32_t pa3 = __float_as_uint(Ps[(row0 + qr + 8) * 68 + kk + qc + 4]);
#pragma unroll
            for (int nt = 0; nt < 8; nt++) {
                const uint32_t b0 = f2tf(Vs[(kk + qc    ) * 72 + nt * 8 + qr]);
                const uint32_t b1 = f2tf(Vs[(kk + qc + 4) * 72 + nt * 8 + qr]);
                mma_tf32(oacc[nt], pa0, pa1, pa2, pa3, b0, b1);
            }
        }
    }

    const float inv0 = 1.f / l0;
    const float inv1 = 1.f / l1;
#pragma unroll
    for (int nt = 0; nt < 8; nt++) {
        float2 w0 = make_float2(oacc[nt][0] * inv0, oacc[nt][1] * inv0);
        float2 w1 = make_float2(oacc[nt][2] * inv1, oacc[nt][3] * inv1);
        *reinterpret_cast<float2*>(&O[(size_t)(q0 + row0 + qr    ) * D + h * HD + nt * 8 + 2 * qc]) = w0;
        *reinterpret_cast<float2*>(&O[(size_t)(q0 + row0 + qr + 8) * D + h * HD + nt * 8 + 2 * qc]) = w1;
    }
}

// ---------------------------------------------------------------------------
extern "C" void kernel_launch(void* const* d_in, const int* in_sizes, int n_in,
                              void* d_out, int out_size)
{
    const float* x_in = (const float*)d_in[0];
    const float* ts   = (const float*)d_in[1];
    const float* ctx  = (const float*)d_in[2];
    const float* rope = (const float*)d_in[3];
    const float* adaW = (const float*)d_in[4];
    const float* adab = (const float*)d_in[5];
    const float* sqW  = (const float*)d_in[6];
    const float* skW  = (const float*)d_in[7];
    const float* svW  = (const float*)d_in[8];
    const float* soW  = (const float*)d_in[9];
    const float* sob  = (const float*)d_in[10];
    const float* cqW  = (const float*)d_in[11];
    const float* ckW  = (const float*)d_in[12];
    const float* cvW  = (const float*)d_in[13];
    const float* coW  = (const float*)d_in[14];
    const float* cob  = (const float*)d_in[15];
    const float* f1W  = (const float*)d_in[16];
    const float* f1b  = (const float*)d_in[17];
    const float* f2W  = (const float*)d_in[18];
    const float* f2b  = (const float*)d_in[19];

    float* x = (float*)d_out;

    float *hx, *q, *k, *v, *o, *ckb, *cvb, *hbuf, *kt, *mods;
    cudaGetSymbolAddress((void**)&hx,   g_hx);
    cudaGetSymbolAddress((void**)&q,    g_q);
    cudaGetSymbolAddress((void**)&k,    g_k);
    cudaGetSymbolAddress((void**)&v,    g_v);
    cudaGetSymbolAddress((void**)&o,    g_o);
    cudaGetSymbolAddress((void**)&ckb,  g_ck);
    cudaGetSymbolAddress((void**)&cvb,  g_cv);
    cudaGetSymbolAddress((void**)&hbuf, g_h);
    cudaGetSymbolAddress((void**)&kt,   g_kt);
    cudaGetSymbolAddress((void**)&mods, g_mods);

    cudaFuncSetAttribute(attn_mma, cudaFuncAttributeMaxDynamicSharedMemorySize, ATTN_SMEM);
    cudaFuncSetAttribute(gemm_tf32, cudaFuncAttributeMaxDynamicSharedMemorySize, GEMM_SMEM);

    cudaMemcpyAsync(x, x_in, (size_t)L * D * sizeof(float), cudaMemcpyDeviceToDevice);

    const float scale = 0.125f; // 64^-0.5
    const dim3 gQKV(D   / 128, L    / 128, 3);
    const dim3 gD  (D   / 128, L    / 128, 1);
    const dim3 gDFF(DFF / 128, L    / 128, 1);
    const dim3 gKV (D   / 128, SCTX / 128, 2);
    const dim3 gAtt(L / 64, H);
    const dim3 gTrS(L / 32,    HD / 32, H);
    const dim3 gTrC(SCTX / 32, HD / 32, H);
    const dim3 bTr(32, 8);

    for (int i = 0; i < NB; i++) {
        const float* adaW_i = adaW + (size_t)i * 6 * D * D;
        const float* adab_i = adab + (size_t)i * 6 * D;
        const float* sqW_i  = sqW  + (size_t)i * D * D;
        const float* skW_i  = skW  + (size_t)i * D * D;
        const float* svW_i  = svW  + (size_t)i * D * D;
        const float* soW_i  = soW  + (size_t)i * D * D;
        const float* sob_i  = sob  + (size_t)i * D;
        const float* cqW_i  = cqW  + (size_t)i * D * D;
        const float* ckW_i  = ckW  + (size_t)i * D * D;
        const float* cvW_i  = cvW  + (size_t)i * D * D;
        const float* coW_i  = coW  + (size_t)i * D * D;
        const float* cob_i  = cob  + (size_t)i * D;
        const float* f1W_i  = f1W  + (size_t)i * DFF * D;
        const float* f1b_i  = f1b  + (size_t)i * DFF;
        const float* f2W_i  = f2W  + (size_t)i * D * DFF;
        const float* f2b_i  = f2b  + (size_t)i * D;

        gemv_ada<<<6 * D / 8, 256>>>(ts, adaW_i, adab_i, mods);

        // --- self attention ---
        ln_mod_kernel<<<L, 256>>>(x, mods, 0, D, hx);
        gemm_tf32<<<gQKV, 256, GEMM_SMEM>>>(hx, sqW_i, skW_i, svW_i, nullptr, nullptr,
                                            q, k, v, L, D, D, EP_STORE);
        rope_kernel<<<(L * H * 32) / 256, 256>>>(q, k, rope);
        transpose_k<<<gTrS, bTr>>>(k, kt, L);
        attn_mma<<<gAtt, 128, ATTN_SMEM>>>(q, kt, v, o, L, scale);
        gemm_tf32<<<gD, 256, GEMM_SMEM>>>(o, soW_i, nullptr, nullptr, sob_i, mods + 2 * D,
                                          x, nullptr, nullptr, L, D, D, EP_RESID_GATE);

        // --- cross attention ---
        ln_mod_kernel<<<L, 256>>>(x, nullptr, 0, 0, hx);
        gemm_tf32<<<gD, 256, GEMM_SMEM>>>(hx, cqW_i, nullptr, nullptr, nullptr, nullptr,
                                          q, nullptr, nullptr, L, D, D, EP_STORE);
        gemm_tf32<<<gKV, 256, GEMM_SMEM>>>(ctx, ckW_i, cvW_i, nullptr, nullptr, nullptr,
                                           ckb, cvb, nullptr, SCTX, D, D, EP_STORE);
        transpose_k<<<gTrC, bTr>>>(ckb, kt, SCTX);
        attn_mma<<<gAtt, 128, ATTN_SMEM>>>(q, kt, cvb, o, SCTX, scale);
        gemm_tf32<<<gD, 256, GEMM_SMEM>>>(o, coW_i, nullptr, nullptr, cob_i, nullptr,
                                          x, nullptr, nullptr, L, D, D, EP_RESID);

        // --- MLP ---
        ln_mod_kernel<<<L, 256>>>(x, mods, 3 * D, 4 * D, hx);
        gemm_tf32<<<gDFF, 256, GEMM_SMEM>>>(hx, f1W_i, nullptr, nullptr, f1b_i, nullptr,
                                            hbuf, nullptr, nullptr, L, DFF, D, EP_GELU);
        gemm_tf32<<<gD, 256, GEMM_SMEM>>>(hbuf, f2W_i, nullptr, nullptr, f2b_i, mods + 5 * D,
                                          x, nullptr, nullptr, L, D, DFF, EP_RESID_GATE);
    }
}

// round 9
// speedup vs baseline: 3.6734x; 1.0091x over previous
#include <cuda_runtime.h>
#include <math.h>
#include <stdint.h>

// Problem constants
constexpr int L    = 3072;
constexpr int D    = 1024;
constexpr int H    = 16;
constexpr int HD   = 64;
constexpr int SCTX = 512;
constexpr int DFF  = 4096;
constexpr int NB   = 2;

// ---------------- scratch (static device arrays; no cudaMalloc allowed) ----
__device__ float g_hx[(size_t)L * D];
__device__ float g_q [(size_t)L * D];
__device__ float g_k [(size_t)L * D];
__device__ float g_v [(size_t)L * D];
__device__ float g_o [(size_t)L * D];
__device__ float g_ck[(size_t)SCTX * D];
__device__ float g_cv[(size_t)SCTX * D];
__device__ float g_h [(size_t)L * DFF];
__device__ float g_kt[(size_t)H * HD * L];   // K^T [h][d][l]
__device__ float g_mods[6 * D];

enum { EP_STORE = 0, EP_GELU = 1, EP_RESID = 2, EP_RESID_GATE = 3 };

__device__ __forceinline__ uint32_t f2tf(float x) {
    uint32_t r;
    asm("cvt.rna.tf32.f32 %0, %1;" : "=r"(r) : "f"(x));
    return r;
}

__device__ __forceinline__ void mma_tf32(float c[4], uint32_t a0, uint32_t a1,
                                         uint32_t a2, uint32_t a3,
                                         uint32_t b0, uint32_t b1) {
    asm volatile(
        "mma.sync.aligned.m16n8k8.row.col.f32.tf32.tf32.f32 "
        "{%0,%1,%2,%3}, {%4,%5,%6,%7}, {%8,%9}, {%0,%1,%2,%3};"
        : "+f"(c[0]), "+f"(c[1]), "+f"(c[2]), "+f"(c[3])
        : "r"(a0), "r"(a1), "r"(a2), "r"(a3), "r"(b0), "r"(b1));
}

__device__ __forceinline__ void cp_async16(uint32_t saddr, const void* gaddr) {
    asm volatile("cp.async.cg.shared.global [%0], [%1], 16;\n"
                 :: "r"(saddr), "l"(gaddr));
}
__device__ __forceinline__ void cp_commit() {
    asm volatile("cp.async.commit_group;\n");
}
template <int N>
__device__ __forceinline__ void cp_wait() {
    asm volatile("cp.async.wait_group %0;\n" :: "n"(N));
}

// ---------------------------------------------------------------------------
// TF32 tensor-core GEMM, 3-stage cp.async pipeline, BK=32 (R6, proven).
// ---------------------------------------------------------------------------
constexpr int GSTAGES = 3;
constexpr int GBK     = 32;
constexpr int GSROW   = 36;                          // 32 + 4 pad
constexpr int GTILE_F = 128 * GSROW;
constexpr int GEMM_SMEM = 2 * GSTAGES * GTILE_F * 4; // 110592 bytes

__global__ void __launch_bounds__(256, 2) gemm_tf32(
    const float* __restrict__ A,
    const float* __restrict__ W0, const float* __restrict__ W1,
    const float* __restrict__ W2,
    const float* __restrict__ bias, const float* __restrict__ gate,
    float* __restrict__ C0, float* __restrict__ C1, float* __restrict__ C2,
    int M, int N, int K, int mode)
{
    extern __shared__ float smem[];
    float* As = smem;
    float* Bs = smem + GSTAGES * GTILE_F;

    const float* W = (blockIdx.z == 0) ? W0 : (blockIdx.z == 1) ? W1 : W2;
    float*       C = (blockIdx.z == 0) ? C0 : (blockIdx.z == 1) ? C1 : C2;

    const int tid  = threadIdx.x;
    const int m0   = blockIdx.y * 128;
    const int n0   = blockIdx.x * 128;
    const int lane = tid & 31;
    const int warp = tid >> 5;
    const int mwb  = (warp & 1) * 64;
    const int nwb  = (warp >> 1) * 32;
    const int qr   = lane >> 2;
    const int qc   = lane & 3;

    const uint32_t sA0 = (uint32_t)__cvta_generic_to_shared(As);
    const uint32_t sB0 = (uint32_t)__cvta_generic_to_shared(Bs);

    const int lrow0 = tid >> 3;
    const int lk    = (tid & 7) * 4;

    float acc[4][4][4];
#pragma unroll
    for (int i = 0; i < 4; i++)
#pragma unroll
        for (int j = 0; j < 4; j++)
#pragma unroll
            for (int e = 0; e < 4; e++) acc[i][j][e] = 0.f;

    const int nT = K / GBK;

    auto ld_stage = [&](int slot, int t) {
        const int kb = t * GBK;
#pragma unroll
        for (int i = 0; i < 4; i++) {
            const int row = lrow0 + i * 32;
            const uint32_t off = (uint32_t)((slot * 128 + row) * GSROW + lk) * 4u;
            cp_async16(sA0 + off, &A[(size_t)(m0 + row) * K + kb + lk]);
            cp_async16(sB0 + off, &W[(size_t)(n0 + row) * K + kb + lk]);
        }
    };

#pragma unroll
    for (int s = 0; s < GSTAGES - 1; s++) {
        if (s < nT) ld_stage(s, s);
        cp_commit();
    }

    int slot = 0;
    for (int t = 0; t < nT; t++) {
        cp_wait<GSTAGES - 2>();
        __syncthreads();

        {
            int ns = slot + 2; if (ns >= GSTAGES) ns -= GSTAGES;
            if (t + GSTAGES - 1 < nT) ld_stage(ns, t + GSTAGES - 1);
            cp_commit();
        }

        const float* At = As + slot * GTILE_F + mwb * GSROW;
        const float* Bt = Bs + slot * GTILE_F + nwb * GSROW;

#pragma unroll
        for (int ks = 0; ks < 4; ks++) {
            const int kk = ks * 8;
            uint32_t afr[4][4], bfr[4][2];
#pragma unroll
            for (int mt = 0; mt < 4; mt++) {
                const int mb = mt * 16;
                afr[mt][0] = f2tf(At[(mb + qr    ) * GSROW + kk + qc    ]);
                afr[mt][1] = f2tf(At[(mb + qr + 8) * GSROW + kk + qc    ]);
                afr[mt][2] = f2tf(At[(mb + qr    ) * GSROW + kk + qc + 4]);
                afr[mt][3] = f2tf(At[(mb + qr + 8) * GSROW + kk + qc + 4]);
            }
#pragma unroll
            for (int nt = 0; nt < 4; nt++) {
                const int nb = nt * 8;
                bfr[nt][0] = f2tf(Bt[(nb + qr) * GSROW + kk + qc    ]);
                bfr[nt][1] = f2tf(Bt[(nb + qr) * GSROW + kk + qc + 4]);
            }
#pragma unroll
            for (int mt = 0; mt < 4; mt++)
#pragma unroll
                for (int nt = 0; nt < 4; nt++)
                    mma_tf32(acc[mt][nt], afr[mt][0], afr[mt][1], afr[mt][2],
                             afr[mt][3], bfr[nt][0], bfr[nt][1]);
        }

        if (++slot >= GSTAGES) slot = 0;
    }

#pragma unroll
    for (int mt = 0; mt < 4; mt++) {
#pragma unroll
        for (int nt = 0; nt < 4; nt++) {
#pragma unroll
            for (int half = 0; half < 2; half++) {
                const int r = m0 + mwb + mt * 16 + qr + half * 8;
#pragma unroll
                for (int e = 0; e < 2; e++) {
                    const int c = n0 + nwb + nt * 8 + 2 * qc + e;
                    float val = acc[mt][nt][half * 2 + e];
                    val += bias ? bias[c] : 0.f;
                    float* Cp = C + (size_t)r * N + c;
                    if (mode == EP_STORE) {
                        *Cp = val;
                    } else if (mode == EP_GELU) {
                        *Cp = 0.5f * val * (1.f + erff(val * 0.70710678118654752f));
                    } else if (mode == EP_RESID) {
                        *Cp += val;
                    } else {
                        *Cp += gate[c] * val;
                    }
                }
            }
        }
    }
}

// ---------------------------------------------------------------------------
// adaLN modulation GEMV
// ---------------------------------------------------------------------------
__global__ void __launch_bounds__(256) gemv_ada(
    const float* __restrict__ t, const float* __restrict__ Wt,
    const float* __restrict__ b, float* __restrict__ out)
{
    const int o    = blockIdx.x * 8 + (threadIdx.x >> 5);
    const int lane = threadIdx.x & 31;
    const float* wr = Wt + (size_t)o * D;
    float s = 0.f;
    for (int d = lane; d < D; d += 32) s = fmaf(t[d], wr[d], s);
#pragma unroll
    for (int off = 16; off; off >>= 1) s += __shfl_xor_sync(0xffffffffu, s, off);
    if (lane == 0) out[o] = s + b[o];
}

// ---------------------------------------------------------------------------
// LayerNorm (+ optional adaLN shift/scale)
// ---------------------------------------------------------------------------
__global__ void __launch_bounds__(256) ln_mod_kernel(
    const float* __restrict__ x, const float* __restrict__ mods,
    int sh_off, int sc_off, float* __restrict__ y)
{
    __shared__ float red[8];
    __shared__ float bval;
    const int row = blockIdx.x;
    const int t = threadIdx.x;
    const float* xr = x + (size_t)row * D;

    float v[4];
    float s = 0.f;
#pragma unroll
    for (int j = 0; j < 4; j++) { v[j] = xr[t + j * 256]; s += v[j]; }
#pragma unroll
    for (int off = 16; off; off >>= 1) s += __shfl_xor_sync(0xffffffffu, s, off);
    if ((t & 31) == 0) red[t >> 5] = s;
    __syncthreads();
    if (t == 0) {
        float tot = 0.f;
        for (int j = 0; j < 8; j++) tot += red[j];
        bval = tot * (1.f / D);
    }
    __syncthreads();
    const float mean = bval;

    float vs = 0.f;
#pragma unroll
    for (int j = 0; j < 4; j++) { float d = v[j] - mean; vs = fmaf(d, d, vs); }
#pragma unroll
    for (int off = 16; off; off >>= 1) vs += __shfl_xor_sync(0xffffffffu, vs, off);
    if ((t & 31) == 0) red[t >> 5] = vs;
    __syncthreads();
    if (t == 0) {
        float tot = 0.f;
        for (int j = 0; j < 8; j++) tot += red[j];
        bval = rsqrtf(tot * (1.f / D) + 1e-6f);
    }
    __syncthreads();
    const float rstd = bval;

    float* yr = y + (size_t)row * D;
#pragma unroll
    for (int j = 0; j < 4; j++) {
        const int d = t + j * 256;
        const float sc = mods ? mods[sc_off + d] : 0.f;
        const float sh = mods ? mods[sh_off + d] : 0.f;
        yr[d] = (v[j] - mean) * rstd * (1.f + sc) + sh;
    }
}

// ---------------------------------------------------------------------------
// RoPE for Q only (in place)
// ---------------------------------------------------------------------------
__global__ void __launch_bounds__(256) rope_q(
    float* __restrict__ q, const float* __restrict__ rope)
{
    const int idx = blockIdx.x * 256 + threadIdx.x;
    if (idx >= L * H * 32) return;
    const int j = idx & 31;
    const int h = (idx >> 5) & 15;
    const int l = idx >> 9;
    const float a1 = rope[l * HD + j];
    const float a2 = rope[l * HD + j + 32];
    const size_t base = (size_t)l * D + h * HD;

    float q1 = q[base + j], q2 = q[base + j + 32];
    q[base + j]      = q1 * cosf(a1) - q2 * sinf(a1);
    q[base + j + 32] = q2 * cosf(a2) + q1 * sinf(a2);
}

// ---------------------------------------------------------------------------
// Fused RoPE(K) + transpose: k [L x D] -> kt [h][d][l], tf32-rounded.
// Block (32,8) handles 32 l x 64 d (one head). Rotation pairs (d, d+32)
// held in registers at load; smem stride 65 conflict-free both phases.
// ---------------------------------------------------------------------------
__global__ void __launch_bounds__(256) rope_k_transpose(
    const float* __restrict__ k, const float* __restrict__ rope,
    float* __restrict__ KT)
{
    __shared__ float s[32][65];
    const int h  = blockIdx.y;
    const int l0 = blockIdx.x * 32;
    const int tx = threadIdx.x, ty = threadIdx.y;

#pragma unroll
    for (int jl = 0; jl < 4; jl++) {
        const int l  = ty + jl * 8;
        const int gl = l0 + l;
        const float v1 = k[(size_t)gl * D + h * HD + tx];
        const float v2 = k[(size_t)gl * D + h * HD + tx + 32];
        const float a1 = rope[gl * HD + tx];
        const float a2 = rope[gl * HD + tx + 32];
        s[l][tx]      = v1 * cosf(a1) - v2 * sinf(a1);
        s[l][tx + 32] = v2 * cosf(a2) + v1 * sinf(a2);
    }
    __syncthreads();

#pragma unroll
    for (int jd = 0; jd < 8; jd++) {
        const int d = ty + jd * 8;
        KT[(size_t)h * HD * L + (size_t)d * L + l0 + tx] =
            __uint_as_float(f2tf(s[tx][d]));
    }
}

// ---------------------------------------------------------------------------
// Plain K transpose (cross-attention; no rope): Kin [Lk x D] -> KT [h][d][l]
// ---------------------------------------------------------------------------
__global__ void __launch_bounds__(256) transpose_k(
    const float* __restrict__ Kin, float* __restrict__ KT, int Lk)
{
    __shared__ float t[32][33];
    const int h  = blockIdx.z;
    const int d0 = blockIdx.y * 32;
    const int l0 = blockIdx.x * 32;
    const int tx = threadIdx.x, ty = threadIdx.y;
#pragma unroll
    for (int j = 0; j < 4; j++)
        t[ty + j * 8][tx] = Kin[(size_t)(l0 + ty + j * 8) * D + h * HD + d0 + tx];
    __syncthreads();
#pragma unroll
    for (int j = 0; j < 4; j++)
        KT[(size_t)h * HD * Lk + (size_t)(d0 + ty + j * 8) * Lk + l0 + tx] =
            __uint_as_float(f2tf(t[tx][ty + j * 8]));
}

// ---------------------------------------------------------------------------
// Tensor-core flash attention (tf32), cp.async overlap, 128 queries/block.
// 8 warps x 16 rows. K 2-stage ring; V single-buffered hidden behind S.
// Strides: Ks/Vs 72 (==8 mod 32), Ps 68 (==4 mod 32) — conflict-free.
// ---------------------------------------------------------------------------
constexpr int ATTN_SMEM = (2 * 64 * 72 + 64 * 72 + 128 * 68) * 4;  // 90112 B

__global__ void __launch_bounds__(256, 2) attn_mma(
    const float* __restrict__ Q, const float* __restrict__ KT,
    const float* __restrict__ Vp, float* __restrict__ O,
    int Lk, float scale)
{
    extern __shared__ float sm[];
    float* Ks = sm;                    // [2][64][72]
    float* Vs = sm + 2 * 64 * 72;      // [64][72]
    float* Ps = sm + 3 * 64 * 72;      // [128][68]

    const int tid  = threadIdx.x;
    const int warp = tid >> 5;
    const int lane = tid & 31;
    const int qr = lane >> 2, qc = lane & 3;
    const int h  = blockIdx.y;
    const int q0 = blockIdx.x * 128;
    const int row0 = warp * 16;

    const float* KTh = KT + (size_t)h * HD * Lk;
    const uint32_t sKs = (uint32_t)__cvta_generic_to_shared(Ks);
    const uint32_t sVs = (uint32_t)__cvta_generic_to_shared(Vs);

    // issue K[0] immediately
    for (int i = tid; i < 64 * 16; i += 256) {
        const int r = i >> 4, c4 = (i & 15) * 4;
        cp_async16(sKs + (uint32_t)(r * 72 + c4) * 4u, &KTh[(size_t)r * Lk + c4]);
    }
    cp_commit();

    // stage Q (scaled) into Ps
    for (int i = tid; i < 128 * 16; i += 256) {
        const int r = i >> 4, c4 = (i & 15) * 4;
        float4 qv = *reinterpret_cast<const float4*>(&Q[(size_t)(q0 + r) * D + h * HD + c4]);
        float* dst = &Ps[r * 68 + c4];
        dst[0] = qv.x * scale; dst[1] = qv.y * scale;
        dst[2] = qv.z * scale; dst[3] = qv.w * scale;
    }
    __syncthreads();

    uint32_t qf[8][4];
#pragma unroll
    for (int ks = 0; ks < 8; ks++) {
        const int kk = ks * 8;
        qf[ks][0] = f2tf(Ps[(row0 + qr    ) * 68 + kk + qc    ]);
        qf[ks][1] = f2tf(Ps[(row0 + qr + 8) * 68 + kk + qc    ]);
        qf[ks][2] = f2tf(Ps[(row0 + qr    ) * 68 + kk + qc + 4]);
        qf[ks][3] = f2tf(Ps[(row0 + qr + 8) * 68 + kk + qc + 4]);
    }

    float m0 = -1e30f, m1 = -1e30f, l0 = 0.f, l1 = 0.f;
    float oacc[8][4];
#pragma unroll
    for (int nt = 0; nt < 8; nt++)
#pragma unroll
        for (int e = 0; e < 4; e++) oacc[nt][e] = 0.f;

    const int nTiles = Lk / 64;
    for (int ti = 0; ti < nTiles; ti++) {
        const int kt = ti * 64;
        float* Kb = Ks + (ti & 1) * 64 * 72;

        cp_wait<0>();        // K[ti] resident (V[ti-1] done earlier)
        __syncthreads();     // all warps done with Vs / other K buf

        // issue V[ti], then K[ti+1]
        for (int i = tid; i < 64 * 16; i += 256) {
            const int r = i >> 4, c4 = (i & 15) * 4;
            cp_async16(sVs + (uint32_t)(r * 72 + c4) * 4u,
                       &Vp[(size_t)(kt + r) * D + h * HD + c4]);
        }
        cp_commit();
        if (ti + 1 < nTiles) {
            const uint32_t kb2 = sKs + (uint32_t)(((ti + 1) & 1) * 64 * 72) * 4u;
            for (int i = tid; i < 64 * 16; i += 256) {
                const int r = i >> 4, c4 = (i & 15) * 4;
                cp_async16(kb2 + (uint32_t)(r * 72 + c4) * 4u,
                           &KTh[(size_t)r * Lk + kt + 64 + c4]);
            }
        }
        cp_commit();

        // S = Q K^T
        float sf[8][4];
#pragma unroll
        for (int nt = 0; nt < 8; nt++)
#pragma unroll
            for (int e = 0; e < 4; e++) sf[nt][e] = 0.f;
#pragma unroll
        for (int ks = 0; ks < 8; ks++) {
            const int kk = ks * 8;
#pragma unroll
            for (int nt = 0; nt < 8; nt++) {
                const uint32_t b0 = __float_as_uint(Kb[(kk + qc    ) * 72 + nt * 8 + qr]);
                const uint32_t b1 = __float_as_uint(Kb[(kk + qc + 4) * 72 + nt * 8 + qr]);
                mma_tf32(sf[nt], qf[ks][0], qf[ks][1], qf[ks][2], qf[ks][3], b0, b1);
            }
        }

        // online softmax
        float rmax0 = -1e30f, rmax1 = -1e30f;
#pragma unroll
        for (int nt = 0; nt < 8; nt++) {
            rmax0 = fmaxf(rmax0, fmaxf(sf[nt][0], sf[nt][1]));
            rmax1 = fmaxf(rmax1, fmaxf(sf[nt][2], sf[nt][3]));
        }
        rmax0 = fmaxf(rmax0, __shfl_xor_sync(0xffffffffu, rmax0, 1));
        rmax0 = fmaxf(rmax0, __shfl_xor_sync(0xffffffffu, rmax0, 2));
        rmax1 = fmaxf(rmax1, __shfl_xor_sync(0xffffffffu, rmax1, 1));
        rmax1 = fmaxf(rmax1, __shfl_xor_sync(0xffffffffu, rmax1, 2));

        const float mn0 = fmaxf(m0, rmax0);
        const float mn1 = fmaxf(m1, rmax1);
        const float a0 = __expf(m0 - mn0);
        const float a1 = __expf(m1 - mn1);
        float rs0 = 0.f, rs1 = 0.f;
#pragma unroll
        for (int nt = 0; nt < 8; nt++) {
            sf[nt][0] = __expf(sf[nt][0] - mn0);
            sf[nt][1] = __expf(sf[nt][1] - mn0);
            sf[nt][2] = __expf(sf[nt][2] - mn1);
            sf[nt][3] = __expf(sf[nt][3] - mn1);
            rs0 += sf[nt][0] + sf[nt][1];
            rs1 += sf[nt][2] + sf[nt][3];
        }
        rs0 += __shfl_xor_sync(0xffffffffu, rs0, 1);
        rs0 += __shfl_xor_sync(0xffffffffu, rs0, 2);
        rs1 += __shfl_xor_sync(0xffffffffu, rs1, 1);
        rs1 += __shfl_xor_sync(0xffffffffu, rs1, 2);
        l0 = l0 * a0 + rs0;
        l1 = l1 * a1 + rs1;
        m0 = mn0; m1 = mn1;
#pragma unroll
        for (int nt = 0; nt < 8; nt++) {
            oacc[nt][0] *= a0; oacc[nt][1] *= a0;
            oacc[nt][2] *= a1; oacc[nt][3] *= a1;
        }

        // P -> warp-private Ps rows (tf32-rounded)
        __syncwarp();
#pragma unroll
        for (int nt = 0; nt < 8; nt++) {
            float2 p0 = make_float2(__uint_as_float(f2tf(sf[nt][0])),
                                    __uint_as_float(f2tf(sf[nt][1])));
            float2 p1 = make_float2(__uint_as_float(f2tf(sf[nt][2])),
                                    __uint_as_float(f2tf(sf[nt][3])));
            *reinterpret_cast<float2*>(&Ps[(row0 + qr    ) * 68 + nt * 8 + 2 * qc]) = p0;
            *reinterpret_cast<float2*>(&Ps[(row0 + qr + 8) * 68 + nt * 8 + 2 * qc]) = p1;
        }
        __syncwarp();

        // V[ti] landed? (K[ti+1] may still be in flight)
        cp_wait<1>();
        __syncthreads();

        // O += P V (V rounded at fragment load)
#pragma unroll
        for (int ks = 0; ks < 8; ks++) {
            const int kk = ks * 8;
            const uint32_t pa0 = __float_as_uint(Ps[(row0 + qr    ) * 68 + kk + qc    ]);
            const uint32_t pa1 = __float_as_uint(Ps[(row0 + qr + 8) * 68 + kk + qc    ]);
            const uint32_t pa2 = __float_as_uint(Ps[(row0 + qr    ) * 68 + kk + qc + 4]);
            const uint32_t pa3 = __float_as_uint(Ps[(row0 + qr + 8) * 68 + kk + qc + 4]);
#pragma unroll
            for (int nt = 0; nt < 8; nt++) {
                const uint32_t b0 = f2tf(Vs[(kk + qc    ) * 72 + nt * 8 + qr]);
                const uint32_t b1 = f2tf(Vs[(kk + qc + 4) * 72 + nt * 8 + qr]);
                mma_tf32(oacc[nt], pa0, pa1, pa2, pa3, b0, b1);
            }
        }
    }

    const float inv0 = 1.f / l0;
    const float inv1 = 1.f / l1;
#pragma unroll
    for (int nt = 0; nt < 8; nt++) {
        float2 w0 = make_float2(oacc[nt][0] * inv0, oacc[nt][1] * inv0);
        float2 w1 = make_float2(oacc[nt][2] * inv1, oacc[nt][3] * inv1);
        *reinterpret_cast<float2*>(&O[(size_t)(q0 + row0 + qr    ) * D + h * HD + nt * 8 + 2 * qc]) = w0;
        *reinterpret_cast<float2*>(&O[(size_t)(q0 + row0 + qr + 8) * D + h * HD + nt * 8 + 2 * qc]) = w1;
    }
}

// ---------------------------------------------------------------------------
extern "C" void kernel_launch(void* const* d_in, const int* in_sizes, int n_in,
                              void* d_out, int out_size)
{
    const float* x_in = (const float*)d_in[0];
    const float* ts   = (const float*)d_in[1];
    const float* ctx  = (const float*)d_in[2];
    const float* rope = (const float*)d_in[3];
    const float* adaW = (const float*)d_in[4];
    const float* adab = (const float*)d_in[5];
    const float* sqW  = (const float*)d_in[6];
    const float* skW  = (const float*)d_in[7];
    const float* svW  = (const float*)d_in[8];
    const float* soW  = (const float*)d_in[9];
    const float* sob  = (const float*)d_in[10];
    const float* cqW  = (const float*)d_in[11];
    const float* ckW  = (const float*)d_in[12];
    const float* cvW  = (const float*)d_in[13];
    const float* coW  = (const float*)d_in[14];
    const float* cob  = (const float*)d_in[15];
    const float* f1W  = (const float*)d_in[16];
    const float* f1b  = (const float*)d_in[17];
    const float* f2W  = (const float*)d_in[18];
    const float* f2b  = (const float*)d_in[19];

    float* x = (float*)d_out;

    float *hx, *q, *k, *v, *o, *ckb, *cvb, *hbuf, *kt, *mods;
    cudaGetSymbolAddress((void**)&hx,   g_hx);
    cudaGetSymbolAddress((void**)&q,    g_q);
    cudaGetSymbolAddress((void**)&k,    g_k);
    cudaGetSymbolAddress((void**)&v,    g_v);
    cudaGetSymbolAddress((void**)&o,    g_o);
    cudaGetSymbolAddress((void**)&ckb,  g_ck);
    cudaGetSymbolAddress((void**)&cvb,  g_cv);
    cudaGetSymbolAddress((void**)&hbuf, g_h);
    cudaGetSymbolAddress((void**)&kt,   g_kt);
    cudaGetSymbolAddress((void**)&mods, g_mods);

    cudaFuncSetAttribute(attn_mma, cudaFuncAttributeMaxDynamicSharedMemorySize, ATTN_SMEM);
    cudaFuncSetAttribute(gemm_tf32, cudaFuncAttributeMaxDynamicSharedMemorySize, GEMM_SMEM);

    cudaMemcpyAsync(x, x_in, (size_t)L * D * sizeof(float), cudaMemcpyDeviceToDevice);

    const float scale = 0.125f; // 64^-0.5
    const dim3 gQKV(D   / 128, L    / 128, 3);
    const dim3 gD  (D   / 128, L    / 128, 1);
    const dim3 gDFF(DFF / 128, L    / 128, 1);
    const dim3 gKV (D   / 128, SCTX / 128, 2);
    const dim3 gAtt(L / 128, H);
    const dim3 gRKT(L / 32, H);
    const dim3 gTrC(SCTX / 32, HD / 32, H);
    const dim3 bTr(32, 8);

    for (int i = 0; i < NB; i++) {
        const float* adaW_i = adaW + (size_t)i * 6 * D * D;
        const float* adab_i = adab + (size_t)i * 6 * D;
        const float* sqW_i  = sqW  + (size_t)i * D * D;
        const float* skW_i  = skW  + (size_t)i * D * D;
        const float* svW_i  = svW  + (size_t)i * D * D;
        const float* soW_i  = soW  + (size_t)i * D * D;
        const float* sob_i  = sob  + (size_t)i * D;
        const float* cqW_i  = cqW  + (size_t)i * D * D;
        const float* ckW_i  = ckW  + (size_t)i * D * D;
        const float* cvW_i  = cvW  + (size_t)i * D * D;
        const float* coW_i  = coW  + (size_t)i * D * D;
        const float* cob_i  = cob  + (size_t)i * D;
        const float* f1W_i  = f1W  + (size_t)i * DFF * D;
        const float* f1b_i  = f1b  + (size_t)i * DFF;
        const float* f2W_i  = f2W  + (size_t)i * D * DFF;
        const float* f2b_i  = f2b  + (size_t)i * D;

        gemv_ada<<<6 * D / 8, 256>>>(ts, adaW_i, adab_i, mods);

        // --- self attention ---
        ln_mod_kernel<<<L, 256>>>(x, mods, 0, D, hx);
        gemm_tf32<<<gQKV, 256, GEMM_SMEM>>>(hx, sqW_i, skW_i, svW_i, nullptr, nullptr,
                                            q, k, v, L, D, D, EP_STORE);
        rope_q<<<(L * H * 32) / 256, 256>>>(q, rope);
        rope_k_transpose<<<gRKT, bTr>>>(k, rope, kt);
        attn_mma<<<gAtt, 256, ATTN_SMEM>>>(q, kt, v, o, L, scale);
        gemm_tf32<<<gD, 256, GEMM_SMEM>>>(o, soW_i, nullptr, nullptr, sob_i, mods + 2 * D,
                                          x, nullptr, nullptr, L, D, D, EP_RESID_GATE);

        // --- cross attention ---
        ln_mod_kernel<<<L, 256>>>(x, nullptr, 0, 0, hx);
        gemm_tf32<<<gD, 256, GEMM_SMEM>>>(hx, cqW_i, nullptr, nullptr, nullptr, nullptr,
                                          q, nullptr, nullptr, L, D, D, EP_STORE);
        gemm_tf32<<<gKV, 256, GEMM_SMEM>>>(ctx, ckW_i, cvW_i, nullptr, nullptr, nullptr,
                                           ckb, cvb, nullptr, SCTX, D, D, EP_STORE);
        transpose_k<<<gTrC, bTr>>>(ckb, kt, SCTX);
        attn_mma<<<gAtt, 256, ATTN_SMEM>>>(q, kt, cvb, o, SCTX, scale);
        gemm_tf32<<<gD, 256, GEMM_SMEM>>>(o, coW_i, nullptr, nullptr, cob_i, nullptr,
                                          x, nullptr, nullptr, L, D, D, EP_RESID);

        // --- MLP ---
        ln_mod_kernel<<<L, 256>>>(x, mods, 3 * D, 4 * D, hx);
        gemm_tf32<<<gDFF, 256, GEMM_SMEM>>>(hx, f1W_i, nullptr, nullptr, f1b_i, nullptr,
                                            hbuf, nullptr, nullptr, L, DFF, D, EP_GELU);
        gemm_tf32<<<gD, 256, GEMM_SMEM>>>(hbuf, f2W_i, nullptr, nullptr, f2b_i, mods + 5 * D,
                                          x, nullptr, nullptr, L, D, DFF, EP_RESID_GATE);
    }
}

// round 10
// speedup vs baseline: 3.7900x; 1.0317x over previous
#include <cuda_runtime.h>
#include <math.h>
#include <stdint.h>

// Problem constants
constexpr int L    = 3072;
constexpr int D    = 1024;
constexpr int H    = 16;
constexpr int HD   = 64;
constexpr int SCTX = 512;
constexpr int DFF  = 4096;
constexpr int NB   = 2;

// ---------------- scratch (static device arrays; no cudaMalloc allowed) ----
__device__ float g_hx[(size_t)L * D];
__device__ float g_q [(size_t)L * D];
__device__ float g_k [(size_t)L * D];
__device__ float g_v [(size_t)L * D];
__device__ float g_o [(size_t)L * D];
__device__ float g_ck[(size_t)SCTX * D];
__device__ float g_cv[(size_t)SCTX * D];
__device__ float g_h [(size_t)L * DFF];
__device__ float g_kt[(size_t)H * HD * L];      // K^T [h][d][l]
__device__ float g_w [(size_t)16 * D * D];      // tf32-rounded weights for one block-iter
__device__ float g_ctx[(size_t)SCTX * D];       // tf32-rounded context
__device__ float g_mods[6 * D];

enum { EP_STORE = 0, EP_GELU = 1, EP_RESID = 2, EP_RESID_GATE = 3 };

__device__ __forceinline__ uint32_t f2tf(float x) {
    uint32_t r;
    asm("cvt.rna.tf32.f32 %0, %1;" : "=r"(r) : "f"(x));
    return r;
}
__device__ __forceinline__ float f2tf_f(float x) { return __uint_as_float(f2tf(x)); }

__device__ __forceinline__ void mma_tf32(float c[4], uint32_t a0, uint32_t a1,
                                         uint32_t a2, uint32_t a3,
                                         uint32_t b0, uint32_t b1) {
    asm volatile(
        "mma.sync.aligned.m16n8k8.row.col.f32.tf32.tf32.f32 "
        "{%0,%1,%2,%3}, {%4,%5,%6,%7}, {%8,%9}, {%0,%1,%2,%3};"
        : "+f"(c[0]), "+f"(c[1]), "+f"(c[2]), "+f"(c[3])
        : "r"(a0), "r"(a1), "r"(a2), "r"(a3), "r"(b0), "r"(b1));
}

__device__ __forceinline__ void cp_async16(uint32_t saddr, const void* gaddr) {
    asm volatile("cp.async.cg.shared.global [%0], [%1], 16;\n"
                 :: "r"(saddr), "l"(gaddr));
}
__device__ __forceinline__ void cp_commit() {
    asm volatile("cp.async.commit_group;\n");
}
template <int N>
__device__ __forceinline__ void cp_wait() {
    asm volatile("cp.async.wait_group %0;\n" :: "n"(N));
}

// ---------------------------------------------------------------------------
// Weight pre-round: 10 per-iter weight slices -> g_w, tf32 (RNA).
// z 0..7: D*D (sq,sk,sv,so,cq,ck,cv,co) at offsets z*D*D
// z 8: f1W (4*D*D) at 8*D*D ; z 9: f2W (4*D*D) at 12*D*D
// ---------------------------------------------------------------------------
__global__ void __launch_bounds__(256) round_w10(
    const float* s0, const float* s1, const float* s2, const float* s3,
    const float* s4, const float* s5, const float* s6, const float* s7,
    const float* s8, const float* s9, float* dst)
{
    const int z = blockIdx.z;
    const float* src;
    size_t cnt, off;
    const size_t DD = (size_t)D * D;
    switch (z) {
        case 0: src = s0; cnt = DD;     off = 0;       break;
        case 1: src = s1; cnt = DD;     off = DD;      break;
        case 2: src = s2; cnt = DD;     off = 2 * DD;  break;
        case 3: src = s3; cnt = DD;     off = 3 * DD;  break;
        case 4: src = s4; cnt = DD;     off = 4 * DD;  break;
        case 5: src = s5; cnt = DD;     off = 5 * DD;  break;
        case 6: src = s6; cnt = DD;     off = 6 * DD;  break;
        case 7: src = s7; cnt = DD;     off = 7 * DD;  break;
        case 8: src = s8; cnt = 4 * DD; off = 8 * DD;  break;
        default: src = s9; cnt = 4 * DD; off = 12 * DD; break;
    }
    const size_t i = ((size_t)blockIdx.x * 256 + threadIdx.x) * 4;
    if (i >= cnt) return;
    float4 v = *reinterpret_cast<const float4*>(src + i);
    v.x = f2tf_f(v.x); v.y = f2tf_f(v.y); v.z = f2tf_f(v.z); v.w = f2tf_f(v.w);
    *reinterpret_cast<float4*>(dst + off + i) = v;
}

// generic array round (for ctx)
__global__ void __launch_bounds__(256) round_arr(
    const float* __restrict__ src, float* __restrict__ dst, size_t n4)
{
    const size_t i = ((size_t)blockIdx.x * 256 + threadIdx.x) * 4;
    if (i >= n4 * 4) return;
    float4 v = *reinterpret_cast<const float4*>(src + i);
    v.x = f2tf_f(v.x); v.y = f2tf_f(v.y); v.z = f2tf_f(v.z); v.w = f2tf_f(v.w);
    *reinterpret_cast<float4*>(dst + i) = v;
}

// ---------------------------------------------------------------------------
// TF32 tensor-core GEMM, 3-stage cp.async pipeline, BK=32.
// ALL inputs pre-rounded to tf32 -> no cvt in the inner loop (raw bit loads).
// ---------------------------------------------------------------------------
constexpr int GSTAGES = 3;
constexpr int GBK     = 32;
constexpr int GSROW   = 36;                          // 32 + 4 pad
constexpr int GTILE_F = 128 * GSROW;
constexpr int GEMM_SMEM = 2 * GSTAGES * GTILE_F * 4; // 110592 bytes

__global__ void __launch_bounds__(256, 2) gemm_tf32(
    const float* __restrict__ A,
    const float* __restrict__ W0, const float* __restrict__ W1,
    const float* __restrict__ W2,
    const float* __restrict__ bias, const float* __restrict__ gate,
    float* __restrict__ C0, float* __restrict__ C1, float* __restrict__ C2,
    int M, int N, int K, int mode)
{
    extern __shared__ float smem[];
    float* As = smem;
    float* Bs = smem + GSTAGES * GTILE_F;

    const float* W = (blockIdx.z == 0) ? W0 : (blockIdx.z == 1) ? W1 : W2;
    float*       C = (blockIdx.z == 0) ? C0 : (blockIdx.z == 1) ? C1 : C2;

    const int tid  = threadIdx.x;
    const int m0   = blockIdx.y * 128;
    const int n0   = blockIdx.x * 128;
    const int lane = tid & 31;
    const int warp = tid >> 5;
    const int mwb  = (warp & 1) * 64;
    const int nwb  = (warp >> 1) * 32;
    const int qr   = lane >> 2;
    const int qc   = lane & 3;

    const uint32_t sA0 = (uint32_t)__cvta_generic_to_shared(As);
    const uint32_t sB0 = (uint32_t)__cvta_generic_to_shared(Bs);

    const int lrow0 = tid >> 3;
    const int lk    = (tid & 7) * 4;

    float acc[4][4][4];
#pragma unroll
    for (int i = 0; i < 4; i++)
#pragma unroll
        for (int j = 0; j < 4; j++)
#pragma unroll
            for (int e = 0; e < 4; e++) acc[i][j][e] = 0.f;

    const int nT = K / GBK;

    auto ld_stage = [&](int slot, int t) {
        const int kb = t * GBK;
#pragma unroll
        for (int i = 0; i < 4; i++) {
            const int row = lrow0 + i * 32;
            const uint32_t off = (uint32_t)((slot * 128 + row) * GSROW + lk) * 4u;
            cp_async16(sA0 + off, &A[(size_t)(m0 + row) * K + kb + lk]);
            cp_async16(sB0 + off, &W[(size_t)(n0 + row) * K + kb + lk]);
        }
    };

#pragma unroll
    for (int s = 0; s < GSTAGES - 1; s++) {
        if (s < nT) ld_stage(s, s);
        cp_commit();
    }

    int slot = 0;
    for (int t = 0; t < nT; t++) {
        cp_wait<GSTAGES - 2>();
        __syncthreads();

        {
            int ns = slot + 2; if (ns >= GSTAGES) ns -= GSTAGES;
            if (t + GSTAGES - 1 < nT) ld_stage(ns, t + GSTAGES - 1);
            cp_commit();
        }

        const float* At = As + slot * GTILE_F + mwb * GSROW;
        const float* Bt = Bs + slot * GTILE_F + nwb * GSROW;

#pragma unroll
        for (int ks = 0; ks < 4; ks++) {
            const int kk = ks * 8;
            uint32_t afr[4][4], bfr[4][2];
#pragma unroll
            for (int mt = 0; mt < 4; mt++) {
                const int mb = mt * 16;
                afr[mt][0] = __float_as_uint(At[(mb + qr    ) * GSROW + kk + qc    ]);
                afr[mt][1] = __float_as_uint(At[(mb + qr + 8) * GSROW + kk + qc    ]);
                afr[mt][2] = __float_as_uint(At[(mb + qr    ) * GSROW + kk + qc + 4]);
                afr[mt][3] = __float_as_uint(At[(mb + qr + 8) * GSROW + kk + qc + 4]);
            }
#pragma unroll
            for (int nt = 0; nt < 4; nt++) {
                const int nb = nt * 8;
                bfr[nt][0] = __float_as_uint(Bt[(nb + qr) * GSROW + kk + qc    ]);
                bfr[nt][1] = __float_as_uint(Bt[(nb + qr) * GSROW + kk + qc + 4]);
            }
#pragma unroll
            for (int mt = 0; mt < 4; mt++)
#pragma unroll
                for (int nt = 0; nt < 4; nt++)
                    mma_tf32(acc[mt][nt], afr[mt][0], afr[mt][1], afr[mt][2],
                             afr[mt][3], bfr[nt][0], bfr[nt][1]);
        }

        if (++slot >= GSTAGES) slot = 0;
    }

#pragma unroll
    for (int mt = 0; mt < 4; mt++) {
#pragma unroll
        for (int nt = 0; nt < 4; nt++) {
#pragma unroll
            for (int half = 0; half < 2; half++) {
                const int r = m0 + mwb + mt * 16 + qr + half * 8;
#pragma unroll
                for (int e = 0; e < 2; e++) {
                    const int c = n0 + nwb + nt * 8 + 2 * qc + e;
                    float val = acc[mt][nt][half * 2 + e];
                    val += bias ? bias[c] : 0.f;
                    float* Cp = C + (size_t)r * N + c;
                    if (mode == EP_STORE) {
                        *Cp = val;
                    } else if (mode == EP_GELU) {
                        // rounded: consumed as tf32 GEMM A-input (f2)
                        *Cp = f2tf_f(0.5f * val * (1.f + erff(val * 0.70710678118654752f)));
                    } else if (mode == EP_RESID) {
                        *Cp += val;
                    } else {
                        *Cp += gate[c] * val;
                    }
                }
            }
        }
    }
}

// ---------------------------------------------------------------------------
// adaLN modulation GEMV
// ---------------------------------------------------------------------------
__global__ void __launch_bounds__(256) gemv_ada(
    const float* __restrict__ t, const float* __restrict__ Wt,
    const float* __restrict__ b, float* __restrict__ out)
{
    const int o    = blockIdx.x * 8 + (threadIdx.x >> 5);
    const int lane = threadIdx.x & 31;
    const float* wr = Wt + (size_t)o * D;
    float s = 0.f;
    for (int d = lane; d < D; d += 32) s = fmaf(t[d], wr[d], s);
#pragma unroll
    for (int off = 16; off; off >>= 1) s += __shfl_xor_sync(0xffffffffu, s, off);
    if (lane == 0) out[o] = s + b[o];
}

// ---------------------------------------------------------------------------
// LayerNorm (+ optional adaLN shift/scale); output tf32-rounded (GEMM A-input)
// ---------------------------------------------------------------------------
__global__ void __launch_bounds__(256) ln_mod_kernel(
    const float* __restrict__ x, const float* __restrict__ mods,
    int sh_off, int sc_off, float* __restrict__ y)
{
    __shared__ float red[8];
    __shared__ float bval;
    const int row = blockIdx.x;
    const int t = threadIdx.x;
    const float* xr = x + (size_t)row * D;

    float v[4];
    float s = 0.f;
#pragma unroll
    for (int j = 0; j < 4; j++) { v[j] = xr[t + j * 256]; s += v[j]; }
#pragma unroll
    for (int off = 16; off; off >>= 1) s += __shfl_xor_sync(0xffffffffu, s, off);
    if ((t & 31) == 0) red[t >> 5] = s;
    __syncthreads();
    if (t == 0) {
        float tot = 0.f;
        for (int j = 0; j < 8; j++) tot += red[j];
        bval = tot * (1.f / D);
    }
    __syncthreads();
    const float mean = bval;

    float vs = 0.f;
#pragma unroll
    for (int j = 0; j < 4; j++) { float d = v[j] - mean; vs = fmaf(d, d, vs); }
#pragma unroll
    for (int off = 16; off; off >>= 1) vs += __shfl_xor_sync(0xffffffffu, vs, off);
    if ((t & 31) == 0) red[t >> 5] = vs;
    __syncthreads();
    if (t == 0) {
        float tot = 0.f;
        for (int j = 0; j < 8; j++) tot += red[j];
        bval = rsqrtf(tot * (1.f / D) + 1e-6f);
    }
    __syncthreads();
    const float rstd = bval;

    float* yr = y + (size_t)row * D;
#pragma unroll
    for (int j = 0; j < 4; j++) {
        const int d = t + j * 256;
        const float sc = mods ? mods[sc_off + d] : 0.f;
        const float sh = mods ? mods[sh_off + d] : 0.f;
        yr[d] = f2tf_f((v[j] - mean) * rstd * (1.f + sc) + sh);
    }
}

// ---------------------------------------------------------------------------
// Fused RoPE(K) + transpose: k [L x D] -> kt [h][d][l], tf32-rounded.
// ---------------------------------------------------------------------------
__global__ void __launch_bounds__(256) rope_k_transpose(
    const float* __restrict__ k, const float* __restrict__ rope,
    float* __restrict__ KT)
{
    __shared__ float s[32][65];
    const int h  = blockIdx.y;
    const int l0 = blockIdx.x * 32;
    const int tx = threadIdx.x, ty = threadIdx.y;

#pragma unroll
    for (int jl = 0; jl < 4; jl++) {
        const int l  = ty + jl * 8;
        const int gl = l0 + l;
        const float v1 = k[(size_t)gl * D + h * HD + tx];
        const float v2 = k[(size_t)gl * D + h * HD + tx + 32];
        const float a1 = rope[gl * HD + tx];
        const float a2 = rope[gl * HD + tx + 32];
        s[l][tx]      = v1 * cosf(a1) - v2 * sinf(a1);
        s[l][tx + 32] = v2 * cosf(a2) + v1 * sinf(a2);
    }
    __syncthreads();

#pragma unroll
    for (int jd = 0; jd < 8; jd++) {
        const int d = ty + jd * 8;
        KT[(size_t)h * HD * L + (size_t)d * L + l0 + tx] = f2tf_f(s[tx][d]);
    }
}

// ---------------------------------------------------------------------------
// Plain K transpose (cross-attention; no rope): Kin [Lk x D] -> KT [h][d][l]
// ---------------------------------------------------------------------------
__global__ void __launch_bounds__(256) transpose_k(
    const float* __restrict__ Kin, float* __restrict__ KT, int Lk)
{
    __shared__ float t[32][33];
    const int h  = blockIdx.z;
    const int d0 = blockIdx.y * 32;
    const int l0 = blockIdx.x * 32;
    const int tx = threadIdx.x, ty = threadIdx.y;
#pragma unroll
    for (int j = 0; j < 4; j++)
        t[ty + j * 8][tx] = Kin[(size_t)(l0 + ty + j * 8) * D + h * HD + d0 + tx];
    __syncthreads();
#pragma unroll
    for (int j = 0; j < 4; j++)
        KT[(size_t)h * HD * Lk + (size_t)(d0 + ty + j * 8) * Lk + l0 + tx] =
            f2tf_f(t[tx][ty + j * 8]);
}

// ---------------------------------------------------------------------------
// Tensor-core flash attention (tf32), cp.async overlap, 128 queries/block.
// Optional fused RoPE on Q (ropePtr != null for self-attention).
// O output tf32-rounded (GEMM A-input for the out-projection).
// ---------------------------------------------------------------------------
constexpr int ATTN_SMEM = (2 * 64 * 72 + 64 * 72 + 128 * 68) * 4;  // 90112 B

__global__ void __launch_bounds__(256, 2) attn_mma(
    const float* __restrict__ Q, const float* __restrict__ KT,
    const float* __restrict__ Vp, float* __restrict__ O,
    const float* __restrict__ ropePtr, int Lk, float scale)
{
    extern __shared__ float sm[];
    float* Ks = sm;                    // [2][64][72]
    float* Vs = sm + 2 * 64 * 72;      // [64][72]
    float* Ps = sm + 3 * 64 * 72;      // [128][68]

    const int tid  = threadIdx.x;
    const int warp = tid >> 5;
    const int lane = tid & 31;
    const int qr = lane >> 2, qc = lane & 3;
    const int h  = blockIdx.y;
    const int q0 = blockIdx.x * 128;
    const int row0 = warp * 16;

    const float* KTh = KT + (size_t)h * HD * Lk;
    const uint32_t sKs = (uint32_t)__cvta_generic_to_shared(Ks);
    const uint32_t sVs = (uint32_t)__cvta_generic_to_shared(Vs);

    // issue K[0] immediately
    for (int i = tid; i < 64 * 16; i += 256) {
        const int r = i >> 4, c4 = (i & 15) * 4;
        cp_async16(sKs + (uint32_t)(r * 72 + c4) * 4u, &KTh[(size_t)r * Lk + c4]);
    }
    cp_commit();

    // stage Q into Ps (with optional fused RoPE), scaled
    if (ropePtr) {
        for (int i = tid; i < 128 * 8; i += 256) {
            const int r = i >> 3, j4 = (i & 7) * 4;
            const int gl = q0 + r;
            float4 q1 = *reinterpret_cast<const float4*>(&Q[(size_t)gl * D + h * HD + j4]);
            float4 q2 = *reinterpret_cast<const float4*>(&Q[(size_t)gl * D + h * HD + j4 + 32]);
            float4 a1 = *reinterpret_cast<const float4*>(&ropePtr[gl * HD + j4]);
            float4 a2 = *reinterpret_cast<const float4*>(&ropePtr[gl * HD + j4 + 32]);
            float* d1 = &Ps[r * 68 + j4];
            float* d2 = &Ps[r * 68 + j4 + 32];
            d1[0] = (q1.x * cosf(a1.x) - q2.x * sinf(a1.x)) * scale;
            d1[1] = (q1.y * cosf(a1.y) - q2.y * sinf(a1.y)) * scale;
            d1[2] = (q1.z * cosf(a1.z) - q2.z * sinf(a1.z)) * scale;
            d1[3] = (q1.w * cosf(a1.w) - q2.w * sinf(a1.w)) * scale;
            d2[0] = (q2.x * cosf(a2.x) + q1.x * sinf(a2.x)) * scale;
            d2[1] = (q2.y * cosf(a2.y) + q1.y * sinf(a2.y)) * scale;
            d2[2] = (q2.z * cosf(a2.z) + q1.z * sinf(a2.z)) * scale;
            d2[3] = (q2.w * cosf(a2.w) + q1.w * sinf(a2.w)) * scale;
        }
    } else {
        for (int i = tid; i < 128 * 16; i += 256) {
            const int r = i >> 4, c4 = (i & 15) * 4;
            float4 qv = *reinterpret_cast<const float4*>(&Q[(size_t)(q0 + r) * D + h * HD + c4]);
            float* dst = &Ps[r * 68 + c4];
            dst[0] = qv.x * scale; dst[1] = qv.y * scale;
            dst[2] = qv.z * scale; dst[3] = qv.w * scale;
        }
    }
    __syncthreads();

    uint32_t qf[8][4];
#pragma unroll
    for (int ks = 0; ks < 8; ks++) {
        const int kk = ks * 8;
        qf[ks][0] = f2tf(Ps[(row0 + qr    ) * 68 + kk + qc    ]);
        qf[ks][1] = f2tf(Ps[(row0 + qr + 8) * 68 + kk + qc    ]);
        qf[ks][2] = f2tf(Ps[(row0 + qr    ) * 68 + kk + qc + 4]);
        qf[ks][3] = f2tf(Ps[(row0 + qr + 8) * 68 + kk + qc + 4]);
    }

    float m0 = -1e30f, m1 = -1e30f, l0 = 0.f, l1 = 0.f;
    float oacc[8][4];
#pragma unroll
    for (int nt = 0; nt < 8; nt++)
#pragma unroll
        for (int e = 0; e < 4; e++) oacc[nt][e] = 0.f;

    const int nTiles = Lk / 64;
    for (int ti = 0; ti < nTiles; ti++) {
        const int kt = ti * 64;
        float* Kb = Ks + (ti & 1) * 64 * 72;

        cp_wait<0>();        // K[ti] resident (V[ti-1] done earlier)
        __syncthreads();     // all warps done with Vs / other K buf

        // issue V[ti], then K[ti+1]
        for (int i = tid; i < 64 * 16; i += 256) {
            const int r = i >> 4, c4 = (i & 15) * 4;
            cp_async16(sVs + (uint32_t)(r * 72 + c4) * 4u,
                       &Vp[(size_t)(kt + r) * D + h * HD + c4]);
        }
        cp_commit();
        if (ti + 1 < nTiles) {
            const uint32_t kb2 = sKs + (uint32_t)(((ti + 1) & 1) * 64 * 72) * 4u;
            for (int i = tid; i < 64 * 16; i += 256) {
                const int r = i >> 4, c4 = (i & 15) * 4;
                cp_async16(kb2 + (uint32_t)(r * 72 + c4) * 4u,
                           &KTh[(size_t)r * Lk + kt + 64 + c4]);
            }
        }
        cp_commit();

        // S = Q K^T
        float sf[8][4];
#pragma unroll
        for (int nt = 0; nt < 8; nt++)
#pragma unroll
            for (int e = 0; e < 4; e++) sf[nt][e] = 0.f;
#pragma unroll
        for (int ks = 0; ks < 8; ks++) {
            const int kk = ks * 8;
#pragma unroll
            for (int nt = 0; nt < 8; nt++) {
                const uint32_t b0 = __float_as_uint(Kb[(kk + qc    ) * 72 + nt * 8 + qr]);
                const uint32_t b1 = __float_as_uint(Kb[(kk + qc + 4) * 72 + nt * 8 + qr]);
                mma_tf32(sf[nt], qf[ks][0], qf[ks][1], qf[ks][2], qf[ks][3], b0, b1);
            }
        }

        // online softmax
        float rmax0 = -1e30f, rmax1 = -1e30f;
#pragma unroll
        for (int nt = 0; nt < 8; nt++) {
            rmax0 = fmaxf(rmax0, fmaxf(sf[nt][0], sf[nt][1]));
            rmax1 = fmaxf(rmax1, fmaxf(sf[nt][2], sf[nt][3]));
        }
        rmax0 = fmaxf(rmax0, __shfl_xor_sync(0xffffffffu, rmax0, 1));
        rmax0 = fmaxf(rmax0, __shfl_xor_sync(0xffffffffu, rmax0, 2));
        rmax1 = fmaxf(rmax1, __shfl_xor_sync(0xffffffffu, rmax1, 1));
        rmax1 = fmaxf(rmax1, __shfl_xor_sync(0xffffffffu, rmax1, 2));

        const float mn0 = fmaxf(m0, rmax0);
        const float mn1 = fmaxf(m1, rmax1);
        const float a0 = __expf(m0 - mn0);
        const float a1 = __expf(m1 - mn1);
        float rs0 = 0.f, rs1 = 0.f;
#pragma unroll
        for (int nt = 0; nt < 8; nt++) {
            sf[nt][0] = __expf(sf[nt][0] - mn0);
            sf[nt][1] = __expf(sf[nt][1] - mn0);
            sf[nt][2] = __expf(sf[nt][2] - mn1);
            sf[nt][3] = __expf(sf[nt][3] - mn1);
            rs0 += sf[nt][0] + sf[nt][1];
            rs1 += sf[nt][2] + sf[nt][3];
        }
        rs0 += __shfl_xor_sync(0xffffffffu, rs0, 1);
        rs0 += __shfl_xor_sync(0xffffffffu, rs0, 2);
        rs1 += __shfl_xor_sync(0xffffffffu, rs1, 1);
        rs1 += __shfl_xor_sync(0xffffffffu, rs1, 2);
        l0 = l0 * a0 + rs0;
        l1 = l1 * a1 + rs1;
        m0 = mn0; m1 = mn1;
#pragma unroll
        for (int nt = 0; nt < 8; nt++) {
            oacc[nt][0] *= a0; oacc[nt][1] *= a0;
            oacc[nt][2] *= a1; oacc[nt][3] *= a1;
        }

        // P -> warp-private Ps rows (tf32-rounded)
        __syncwarp();
#pragma unroll
        for (int nt = 0; nt < 8; nt++) {
            float2 p0 = make_float2(f2tf_f(sf[nt][0]), f2tf_f(sf[nt][1]));
            float2 p1 = make_float2(f2tf_f(sf[nt][2]), f2tf_f(sf[nt][3]));
            *reinterpret_cast<float2*>(&Ps[(row0 + qr    ) * 68 + nt * 8 + 2 * qc]) = p0;
            *reinterpret_cast<float2*>(&Ps[(row0 + qr + 8) * 68 + nt * 8 + 2 * qc]) = p1;
        }
        __syncwarp();

        // V[ti] landed? (K[ti+1] may still be in flight)
        cp_wait<1>();
        __syncthreads();

        // O += P V (V rounded at fragment load)
#pragma unroll
        for (int ks = 0; ks < 8; ks++) {
            const int kk = ks * 8;
            const uint32_t pa0 = __float_as_uint(Ps[(row0 + qr    ) * 68 + kk + qc    ]);
            const uint32_t pa1 = __float_as_uint(Ps[(row0 + qr + 8) * 68 + kk + qc    ]);
            const uint32_t pa2 = __float_as_uint(Ps[(row0 + qr    ) * 68 + kk + qc + 4]);
            const uint32_t pa3 = __float_as_uint(Ps[(row0 + qr + 8) * 68 + kk + qc + 4]);
#pragma unroll
            for (int nt = 0; nt < 8; nt++) {
                const uint32_t b0 = f2tf(Vs[(kk + qc    ) * 72 + nt * 8 + qr]);
                const uint32_t b1 = f2tf(Vs[(kk + qc + 4) * 72 + nt * 8 + qr]);
                mma_tf32(oacc[nt], pa0, pa1, pa2, pa3, b0, b1);
            }
        }
    }

    // epilogue: O rounded to tf32 (consumed as GEMM A-input)
    const float inv0 = 1.f / l0;
    const float inv1 = 1.f / l1;
#pragma unroll
    for (int nt = 0; nt < 8; nt++) {
        float2 w0 = make_float2(f2tf_f(oacc[nt][0] * inv0), f2tf_f(oacc[nt][1] * inv0));
        float2 w1 = make_float2(f2tf_f(oacc[nt][2] * inv1), f2tf_f(oacc[nt][3] * inv1));
        *reinterpret_cast<float2*>(&O[(size_t)(q0 + row0 + qr    ) * D + h * HD + nt * 8 + 2 * qc]) = w0;
        *reinterpret_cast<float2*>(&O[(size_t)(q0 + row0 + qr + 8) * D + h * HD + nt * 8 + 2 * qc]) = w1;
    }
}

// ---------------------------------------------------------------------------
extern "C" void kernel_launch(void* const* d_in, const int* in_sizes, int n_in,
                              void* d_out, int out_size)
{
    const float* x_in = (const float*)d_in[0];
    const float* ts   = (const float*)d_in[1];
    const float* ctx  = (const float*)d_in[2];
    const float* rope = (const float*)d_in[3];
    const float* adaW = (const float*)d_in[4];
    const float* adab = (const float*)d_in[5];
    const float* sqW  = (const float*)d_in[6];
    const float* skW  = (const float*)d_in[7];
    const float* svW  = (const float*)d_in[8];
    const float* soW  = (const float*)d_in[9];
    const float* sob  = (const float*)d_in[10];
    const float* cqW  = (const float*)d_in[11];
    const float* ckW  = (const float*)d_in[12];
    const float* cvW  = (const float*)d_in[13];
    const float* coW  = (const float*)d_in[14];
    const float* cob  = (const float*)d_in[15];
    const float* f1W  = (const float*)d_in[16];
    const float* f1b  = (const float*)d_in[17];
    const float* f2W  = (const float*)d_in[18];
    const float* f2b  = (const float*)d_in[19];

    float* x = (float*)d_out;

    float *hx, *q, *k, *v, *o, *ckb, *cvb, *hbuf, *kt, *wr, *ctxr, *mods;
    cudaGetSymbolAddress((void**)&hx,   g_hx);
    cudaGetSymbolAddress((void**)&q,    g_q);
    cudaGetSymbolAddress((void**)&k,    g_k);
    cudaGetSymbolAddress((void**)&v,    g_v);
    cudaGetSymbolAddress((void**)&o,    g_o);
    cudaGetSymbolAddress((void**)&ckb,  g_ck);
    cudaGetSymbolAddress((void**)&cvb,  g_cv);
    cudaGetSymbolAddress((void**)&hbuf, g_h);
    cudaGetSymbolAddress((void**)&kt,   g_kt);
    cudaGetSymbolAddress((void**)&wr,   g_w);
    cudaGetSymbolAddress((void**)&ctxr, g_ctx);
    cudaGetSymbolAddress((void**)&mods, g_mods);

    cudaFuncSetAttribute(attn_mma, cudaFuncAttributeMaxDynamicSharedMemorySize, ATTN_SMEM);
    cudaFuncSetAttribute(gemm_tf32, cudaFuncAttributeMaxDynamicSharedMemorySize, GEMM_SMEM);

    cudaMemcpyAsync(x, x_in, (size_t)L * D * sizeof(float), cudaMemcpyDeviceToDevice);

    const size_t DD = (size_t)D * D;
    const float scale = 0.125f; // 64^-0.5
    const dim3 gQKV(D   / 128, L    / 128, 3);
    const dim3 gD  (D   / 128, L    / 128, 1);
    const dim3 gDFF(DFF / 128, L    / 128, 1);
    const dim3 gKV (D   / 128, SCTX / 128, 2);
    const dim3 gAtt(L / 128, H);
    const dim3 gRKT(L / 32, H);
    const dim3 gTrC(SCTX / 32, HD / 32, H);
    const dim3 bTr(32, 8);
    const dim3 gRW((4 * DD) / 1024, 1, 10);

    // pre-round context once (used both iterations)
    round_arr<<<(SCTX * D) / 1024, 256>>>(ctx, ctxr, (size_t)(SCTX * D) / 4);

    for (int i = 0; i < NB; i++) {
        const float* adaW_i = adaW + (size_t)i * 6 * DD;
        const float* adab_i = adab + (size_t)i * 6 * D;
        const float* sob_i  = sob  + (size_t)i * D;
        const float* cob_i  = cob  + (size_t)i * D;
        const float* f1b_i  = f1b  + (size_t)i * DFF;
        const float* f2b_i  = f2b  + (size_t)i * D;

        // pre-round this iteration's GEMM weights to tf32
        round_w10<<<gRW, 256>>>(sqW + i * DD, skW + i * DD, svW + i * DD, soW + i * DD,
                                cqW + i * DD, ckW + i * DD, cvW + i * DD, coW + i * DD,
                                f1W + (size_t)i * DFF * D, f2W + (size_t)i * D * DFF, wr);

        gemv_ada<<<6 * D / 8, 256>>>(ts, adaW_i, adab_i, mods);

        // --- self attention ---
        ln_mod_kernel<<<L, 256>>>(x, mods, 0, D, hx);
        gemm_tf32<<<gQKV, 256, GEMM_SMEM>>>(hx, wr, wr + DD, wr + 2 * DD, nullptr, nullptr,
                                            q, k, v, L, D, D, EP_STORE);
        rope_k_transpose<<<gRKT, bTr>>>(k, rope, kt);
        attn_mma<<<gAtt, 256, ATTN_SMEM>>>(q, kt, v, o, rope, L, scale);
        gemm_tf32<<<gD, 256, GEMM_SMEM>>>(o, wr + 3 * DD, nullptr, nullptr, sob_i, mods + 2 * D,
                                          x, nullptr, nullptr, L, D, D, EP_RESID_GATE);

        // --- cross attention ---
        ln_mod_kernel<<<L, 256>>>(x, nullptr, 0, 0, hx);
        gemm_tf32<<<gD, 256, GEMM_SMEM>>>(hx, wr + 4 * DD, nullptr, nullptr, nullptr, nullptr,
                                          q, nullptr, nullptr, L, D, D, EP_STORE);
        gemm_tf32<<<gKV, 256, GEMM_SMEM>>>(ctxr, wr + 5 * DD, wr + 6 * DD, nullptr, nullptr, nullptr,
                                           ckb, cvb, nullptr, SCTX, D, D, EP_STORE);
        transpose_k<<<gTrC, bTr>>>(ckb, kt, SCTX);
        attn_mma<<<gAtt, 256, ATTN_SMEM>>>(q, kt, cvb, o, nullptr, SCTX, scale);
        gemm_tf32<<<gD, 256, GEMM_SMEM>>>(o, wr + 7 * DD, nullptr, nullptr, cob_i, nullptr,
                                          x, nullptr, nullptr, L, D, D, EP_RESID);

        // --- MLP ---
        ln_mod_kernel<<<L, 256>>>(x, mods, 3 * D, 4 * D, hx);
        gemm_tf32<<<gDFF, 256, GEMM_SMEM>>>(hx, wr + 8 * DD, nullptr, nullptr, f1b_i, nullptr,
                                            hbuf, nullptr, nullptr, L, DFF, D, EP_GELU);
        gemm_tf32<<<gD, 256, GEMM_SMEM>>>(hbuf, wr + 12 * DD, nullptr, nullptr, f2b_i, mods + 5 * D,
                                          x, nullptr, nullptr, L, D, DFF, EP_RESID_GATE);
    }
}